// round 1
// baseline (speedup 1.0000x reference)
#include <cuda_runtime.h>
#include <cstdint>

// Problem constants
#define BB 2
#define TT 2048
#define CC 1024
#define HH 16
#define DD 64

// Scratch (device globals: allocation-free)
__device__ float g_qkv[BB * TT * 3 * CC];   // [B, T, 3C]  ~50 MB
__device__ float g_y[BB * TT * CC];         // [B, T, C]   ~16 MB

// ---------------------------------------------------------------------------
// NT SGEMM: Cout[m, n] = sum_k A[m*K + k] * W[n*K + k] + bias[n]
// BM = BN = 128, BK = 16, 256 threads, 8x8 per-thread tile.
// ---------------------------------------------------------------------------
__global__ __launch_bounds__(256) void gemm_nt_bias(
    const float* __restrict__ A, const float* __restrict__ W,
    const float* __restrict__ bias, float* __restrict__ Cout,
    int M, int N, int K)
{
    __shared__ float As[16][132];   // k-major, +4 pad
    __shared__ float Bs[16][132];

    const int tid = threadIdx.x;
    const int tx = tid & 15;        // col group
    const int ty = tid >> 4;        // row group
    const int m0 = blockIdx.y * 128;
    const int n0 = blockIdx.x * 128;

    float acc[8][8];
#pragma unroll
    for (int i = 0; i < 8; i++)
#pragma unroll
        for (int j = 0; j < 8; j++) acc[i][j] = 0.0f;

    for (int k0 = 0; k0 < K; k0 += 16) {
        // Load 128x16 tiles of A and W, store k-major (transposed) into smem.
#pragma unroll
        for (int it = 0; it < 2; it++) {
            int idx = it * 256 + tid;       // 0..511
            int row = idx >> 2;             // 0..127
            int c4  = (idx & 3) * 4;        // 0,4,8,12
            float4 va = *(const float4*)(A + (size_t)(m0 + row) * K + k0 + c4);
            As[c4 + 0][row] = va.x;
            As[c4 + 1][row] = va.y;
            As[c4 + 2][row] = va.z;
            As[c4 + 3][row] = va.w;
            float4 vb = *(const float4*)(W + (size_t)(n0 + row) * K + k0 + c4);
            Bs[c4 + 0][row] = vb.x;
            Bs[c4 + 1][row] = vb.y;
            Bs[c4 + 2][row] = vb.z;
            Bs[c4 + 3][row] = vb.w;
        }
        __syncthreads();

#pragma unroll
        for (int kk = 0; kk < 16; kk++) {
            float a[8], b[8];
            *(float4*)&a[0] = *(const float4*)&As[kk][ty * 8];
            *(float4*)&a[4] = *(const float4*)&As[kk][ty * 8 + 4];
            *(float4*)&b[0] = *(const float4*)&Bs[kk][tx * 8];
            *(float4*)&b[4] = *(const float4*)&Bs[kk][tx * 8 + 4];
#pragma unroll
            for (int i = 0; i < 8; i++)
#pragma unroll
                for (int j = 0; j < 8; j++)
                    acc[i][j] = fmaf(a[i], b[j], acc[i][j]);
        }
        __syncthreads();
    }

    // Epilogue with bias
#pragma unroll
    for (int i = 0; i < 8; i++) {
        size_t rb = (size_t)(m0 + ty * 8 + i) * N + n0 + tx * 8;
#pragma unroll
        for (int j4 = 0; j4 < 8; j4 += 4) {
            float4 o;
            o.x = acc[i][j4 + 0] + bias[n0 + tx * 8 + j4 + 0];
            o.y = acc[i][j4 + 1] + bias[n0 + tx * 8 + j4 + 1];
            o.z = acc[i][j4 + 2] + bias[n0 + tx * 8 + j4 + 2];
            o.w = acc[i][j4 + 3] + bias[n0 + tx * 8 + j4 + 3];
            *(float4*)(Cout + rb + j4) = o;
        }
    }
}

// ---------------------------------------------------------------------------
// Flash attention, fp32, causal. 64 queries x 64 keys per tile.
// Grid: (T/64, H, B). 256 threads: tx in [0,16) cols, ty in [0,16) rows,
// 4x4 micro-tile per thread. Row-wise softmax reductions via shfl width 16.
// Dynamic smem: Qs[64][64] + Kt[64][65] + Vs[64][64] + Ps[64][65]
// ---------------------------------------------------------------------------
#define ATTN_SMEM_FLOATS (64 * 64 + 64 * 65 + 64 * 64 + 64 * 65)
#define ATTN_SMEM_BYTES  (ATTN_SMEM_FLOATS * 4)

__global__ __launch_bounds__(256) void flash_attn_kernel(
    const float* __restrict__ qkv, float* __restrict__ y)
{
    extern __shared__ float sm[];
    float* Qs = sm;                      // [64][64] row-major (query, d)
    float* Kt = Qs + 64 * 64;            // [64][65] d-major (d, key)
    float* Vs = Kt + 64 * 65;            // [64][64] row-major (key, d)
    float* Ps = Vs + 64 * 64;            // [64][65]

    const int qi = blockIdx.x;           // query tile 0..31
    const int h  = blockIdx.y;
    const int b  = blockIdx.z;
    const int tid = threadIdx.x;
    const int tx = tid & 15;
    const int ty = tid >> 4;
    const int q0 = qi * 64;
    const float scale = 0.125f;          // 1/sqrt(64)

    const float* base = qkv + (size_t)b * TT * 3 * CC;

    // Load Q tile (scaled), row-major
#pragma unroll
    for (int it = 0; it < 4; it++) {
        int idx = it * 256 + tid;        // 0..1023
        int row = idx >> 4;              // 0..63
        int c4  = (idx & 15) * 4;        // 0..60
        float4 v = *(const float4*)(base + (size_t)(q0 + row) * (3 * CC) + h * DD + c4);
        float4* dst = (float4*)&Qs[row * 64 + c4];
        dst->x = v.x * scale; dst->y = v.y * scale;
        dst->z = v.z * scale; dst->w = v.w * scale;
    }

    float m_i[4], l_i[4], acc[4][4];
#pragma unroll
    for (int i = 0; i < 4; i++) {
        m_i[i] = -1e30f; l_i[i] = 0.0f;
#pragma unroll
        for (int c = 0; c < 4; c++) acc[i][c] = 0.0f;
    }

    const int nkt = qi + 1;              // causal: key tiles 0..qi
    for (int kt = 0; kt < nkt; kt++) {
        const int k0 = kt * 64;
        __syncthreads();                 // prev PV done before overwriting K/V

        // Load K (transposed into Kt) and V (row-major)
#pragma unroll
        for (int it = 0; it < 4; it++) {
            int idx = it * 256 + tid;
            int row = idx >> 4;          // key 0..63
            int c4  = (idx & 15) * 4;
            const float* kp = base + (size_t)(k0 + row) * (3 * CC) + CC + h * DD + c4;
            float4 kv = *(const float4*)kp;
            Kt[(c4 + 0) * 65 + row] = kv.x;
            Kt[(c4 + 1) * 65 + row] = kv.y;
            Kt[(c4 + 2) * 65 + row] = kv.z;
            Kt[(c4 + 3) * 65 + row] = kv.w;
            float4 vv = *(const float4*)(kp + CC);
            *(float4*)&Vs[row * 64 + c4] = vv;
        }
        __syncthreads();

        // S = Q K^T  (s[i][j], rows q0+ty*4+i, cols k0+tx*4+j)
        float s[4][4];
#pragma unroll
        for (int i = 0; i < 4; i++)
#pragma unroll
            for (int j = 0; j < 4; j++) s[i][j] = 0.0f;

#pragma unroll 8
        for (int d = 0; d < 64; d++) {
            float a[4], bv[4];
#pragma unroll
            for (int i = 0; i < 4; i++) a[i] = Qs[(ty * 4 + i) * 64 + d];
#pragma unroll
            for (int j = 0; j < 4; j++) bv[j] = Kt[d * 65 + tx * 4 + j];
#pragma unroll
            for (int i = 0; i < 4; i++)
#pragma unroll
                for (int j = 0; j < 4; j++)
                    s[i][j] = fmaf(a[i], bv[j], s[i][j]);
        }

        // Causal mask (only needed on the diagonal tile)
        if (kt == qi) {
#pragma unroll
            for (int i = 0; i < 4; i++)
#pragma unroll
                for (int j = 0; j < 4; j++)
                    if (k0 + tx * 4 + j > q0 + ty * 4 + i) s[i][j] = -1e30f;
        }

        // Online softmax update per row
#pragma unroll
        for (int i = 0; i < 4; i++) {
            float mloc = fmaxf(fmaxf(s[i][0], s[i][1]), fmaxf(s[i][2], s[i][3]));
#pragma unroll
            for (int o = 8; o >= 1; o >>= 1)
                mloc = fmaxf(mloc, __shfl_xor_sync(0xffffffffu, mloc, o, 16));
            float mnew = fmaxf(m_i[i], mloc);
            float alpha = __expf(m_i[i] - mnew);
            m_i[i] = mnew;
            float lloc = 0.0f;
#pragma unroll
            for (int j = 0; j < 4; j++) {
                float p = __expf(s[i][j] - mnew);
                s[i][j] = p;
                lloc += p;
            }
#pragma unroll
            for (int o = 8; o >= 1; o >>= 1)
                lloc += __shfl_xor_sync(0xffffffffu, lloc, o, 16);
            l_i[i] = l_i[i] * alpha + lloc;
#pragma unroll
            for (int c = 0; c < 4; c++) acc[i][c] *= alpha;
#pragma unroll
            for (int j = 0; j < 4; j++)
                Ps[(ty * 4 + i) * 65 + tx * 4 + j] = s[i][j];
        }
        __syncthreads();

        // acc += P @ V   (cols tx*4..tx*4+3 of D)
#pragma unroll 8
        for (int j = 0; j < 64; j++) {
            float a[4];
#pragma unroll
            for (int i = 0; i < 4; i++) a[i] = Ps[(ty * 4 + i) * 65 + j];
            float4 bv = *(const float4*)&Vs[j * 64 + tx * 4];
#pragma unroll
            for (int i = 0; i < 4; i++) {
                acc[i][0] = fmaf(a[i], bv.x, acc[i][0]);
                acc[i][1] = fmaf(a[i], bv.y, acc[i][1]);
                acc[i][2] = fmaf(a[i], bv.z, acc[i][2]);
                acc[i][3] = fmaf(a[i], bv.w, acc[i][3]);
            }
        }
    }

    // Write out: y[b, q, h*64 + c]
#pragma unroll
    for (int i = 0; i < 4; i++) {
        float inv_l = 1.0f / l_i[i];
        float4 o;
        o.x = acc[i][0] * inv_l;
        o.y = acc[i][1] * inv_l;
        o.z = acc[i][2] * inv_l;
        o.w = acc[i][3] * inv_l;
        *(float4*)(y + (size_t)(b * TT + q0 + ty * 4 + i) * CC + h * DD + tx * 4) = o;
    }
}

// ---------------------------------------------------------------------------
// Launch
// ---------------------------------------------------------------------------
extern "C" void kernel_launch(void* const* d_in, const int* in_sizes, int n_in,
                              void* d_out, int out_size)
{
    const float* x  = (const float*)d_in[0];   // [B,T,C]
    const float* We = (const float*)d_in[1];   // [3C,C]
    const float* be = (const float*)d_in[2];   // [3C]
    const float* Wp = (const float*)d_in[3];   // [C,C]
    const float* bp = (const float*)d_in[4];   // [C]
    float* out = (float*)d_out;                // [B,T,C]

    float* qkv = nullptr;
    float* y = nullptr;
    cudaGetSymbolAddress((void**)&qkv, g_qkv);
    cudaGetSymbolAddress((void**)&y, g_y);

    cudaFuncSetAttribute(flash_attn_kernel,
                         cudaFuncAttributeMaxDynamicSharedMemorySize,
                         ATTN_SMEM_BYTES);

    const int M = BB * TT;   // 4096

    // 1) QKV = x @ We^T + be
    gemm_nt_bias<<<dim3(3 * CC / 128, M / 128), 256>>>(x, We, be, qkv, M, 3 * CC, CC);

    // 2) Flash attention (causal)
    flash_attn_kernel<<<dim3(TT / 64, HH, BB), 256, ATTN_SMEM_BYTES>>>(qkv, y);

    // 3) out = y @ Wp^T + bp
    gemm_nt_bias<<<dim3(CC / 128, M / 128), 256>>>(y, Wp, bp, out, M, CC, CC);
}

// round 2
// speedup vs baseline: 1.1877x; 1.1877x over previous
#include <cuda_runtime.h>
#include <cstdint>

// Problem constants
#define BB 2
#define TT 2048
#define CC 1024
#define HH 16
#define DD 64

// Scratch (device globals: allocation-free)
__device__ float g_qkv[BB * TT * 3 * CC];   // [B, T, 3C]
__device__ float g_y[BB * TT * CC];         // [B, T, C]

// ---------------------------------------------------------------------------
// tf32 helpers
// ---------------------------------------------------------------------------
__device__ __forceinline__ void cp_async16(uint32_t dst, const void* src) {
    asm volatile("cp.async.cg.shared.global [%0], [%1], 16;\n" :: "r"(dst), "l"(src));
}
__device__ __forceinline__ void cp_commit() { asm volatile("cp.async.commit_group;\n"); }
__device__ __forceinline__ void cp_wait0()  { asm volatile("cp.async.wait_group 0;\n"); }

__device__ __forceinline__ void mma_tf32(float c[4],
    uint32_t a0, uint32_t a1, uint32_t a2, uint32_t a3,
    uint32_t b0, uint32_t b1)
{
    asm volatile(
        "mma.sync.aligned.m16n8k8.row.col.f32.tf32.tf32.f32 "
        "{%0,%1,%2,%3}, {%4,%5,%6,%7}, {%8,%9}, {%0,%1,%2,%3};\n"
        : "+f"(c[0]), "+f"(c[1]), "+f"(c[2]), "+f"(c[3])
        : "r"(a0), "r"(a1), "r"(a2), "r"(a3), "r"(b0), "r"(b1));
}

// Split x into hi (tf32-truncated, exact) and lo (residual). HW reads only the
// top 19 bits of a tf32 operand, so lo can be fed as raw fp32 bits.
__device__ __forceinline__ void tf32_split(float x, uint32_t& hi, uint32_t& lo) {
    uint32_t xb = __float_as_uint(x);
    hi = xb & 0xFFFFE000u;
    lo = __float_as_uint(x - __uint_as_float(hi));
}

// ---------------------------------------------------------------------------
// NT GEMM (3xTF32): Cout[m,n] = sum_k A[m,k] * W[n,k] + bias[n]
// Block 128x128x32, 256 threads (8 warps, 2x4), warp tile 64x32.
// smem row stride 36 floats -> all fragment LDS conflict-free.
// ---------------------------------------------------------------------------
#define GPAD 36
#define GEMM_SMEM_BYTES (4 * 128 * GPAD * 4)   // As[2] + Bs[2]

__global__ __launch_bounds__(256) void gemm_nt_tf32(
    const float* __restrict__ A, const float* __restrict__ W,
    const float* __restrict__ bias, float* __restrict__ Cout,
    int M, int N, int K)
{
    extern __shared__ float gsm[];
    float* As = gsm;                   // [2][128][GPAD]
    float* Bs = gsm + 2 * 128 * GPAD;  // [2][128][GPAD]

    const int tid  = threadIdx.x;
    const int wid  = tid >> 5;
    const int lane = tid & 31;
    const int g    = lane >> 2;        // 0..7
    const int cg   = lane & 3;         // 0..3
    const int wM   = wid >> 2;         // 0..1
    const int wN   = wid & 3;          // 0..3
    const int m0   = blockIdx.y * 128;
    const int n0   = blockIdx.x * 128;

    float acc[4][4][4];
#pragma unroll
    for (int mi = 0; mi < 4; mi++)
#pragma unroll
        for (int ni = 0; ni < 4; ni++)
#pragma unroll
            for (int r = 0; r < 4; r++) acc[mi][ni][r] = 0.0f;

    const int NT = K / 32;
    const int row_l = tid >> 3;          // 0..31 per 256-thread chunk? (idx based below)

    // --- load tile kt into buffer buf ---
    auto load_tile = [&](int kt, int buf) {
        const int k0 = kt * 32;
        float* dA = As + buf * 128 * GPAD;
        float* dB = Bs + buf * 128 * GPAD;
#pragma unroll
        for (int it = 0; it < 4; it++) {
            int idx = it * 256 + tid;        // 0..1023
            int row = idx >> 3;              // 0..127
            int c4  = (idx & 7) * 4;         // 0..28
            uint32_t da = (uint32_t)__cvta_generic_to_shared(dA + row * GPAD + c4);
            cp_async16(da, A + (size_t)(m0 + row) * K + k0 + c4);
            uint32_t db = (uint32_t)__cvta_generic_to_shared(dB + row * GPAD + c4);
            cp_async16(db, W + (size_t)(n0 + row) * K + k0 + c4);
        }
    };

    load_tile(0, 0);
    cp_commit();

    for (int kt = 0; kt < NT; kt++) {
        cp_wait0();
        __syncthreads();
        if (kt + 1 < NT) {
            load_tile(kt + 1, (kt + 1) & 1);
            cp_commit();
        }

        const float* Ab = As + (kt & 1) * 128 * GPAD + (wM * 64) * GPAD;
        const float* Bb = Bs + (kt & 1) * 128 * GPAD + (wN * 32) * GPAD;

#pragma unroll
        for (int ks = 0; ks < 4; ks++) {
            uint32_t ahi[4][4], alo[4][4];
#pragma unroll
            for (int mi = 0; mi < 4; mi++) {
                const float* ap = Ab + (mi * 16 + g) * GPAD + ks * 8 + cg;
                float x0 = ap[0];            // (g,   c)
                float x1 = ap[8 * GPAD];     // (g+8, c)
                float x2 = ap[4];            // (g,   c+4)
                float x3 = ap[8 * GPAD + 4]; // (g+8, c+4)
                tf32_split(x0, ahi[mi][0], alo[mi][0]);
                tf32_split(x1, ahi[mi][1], alo[mi][1]);
                tf32_split(x2, ahi[mi][2], alo[mi][2]);
                tf32_split(x3, ahi[mi][3], alo[mi][3]);
            }
#pragma unroll
            for (int ni = 0; ni < 4; ni++) {
                const float* bp = Bb + (ni * 8 + g) * GPAD + ks * 8 + cg;
                float y0 = bp[0];            // (k=c,   n=g)
                float y1 = bp[4];            // (k=c+4, n=g)
                uint32_t bhi0, blo0, bhi1, blo1;
                tf32_split(y0, bhi0, blo0);
                tf32_split(y1, bhi1, blo1);
#pragma unroll
                for (int mi = 0; mi < 4; mi++) {
                    mma_tf32(acc[mi][ni], ahi[mi][0], ahi[mi][1], ahi[mi][2], ahi[mi][3], bhi0, bhi1);
                    mma_tf32(acc[mi][ni], ahi[mi][0], ahi[mi][1], ahi[mi][2], ahi[mi][3], blo0, blo1);
                    mma_tf32(acc[mi][ni], alo[mi][0], alo[mi][1], alo[mi][2], alo[mi][3], bhi0, bhi1);
                }
            }
        }
        __syncthreads();
    }

    // Epilogue with bias
#pragma unroll
    for (int mi = 0; mi < 4; mi++) {
        int r0 = m0 + wM * 64 + mi * 16 + g;
#pragma unroll
        for (int ni = 0; ni < 4; ni++) {
            int col = n0 + wN * 32 + ni * 8 + 2 * cg;
            float b0v = bias[col], b1v = bias[col + 1];
            float2 o1 = { acc[mi][ni][0] + b0v, acc[mi][ni][1] + b1v };
            float2 o2 = { acc[mi][ni][2] + b0v, acc[mi][ni][3] + b1v };
            *(float2*)(Cout + (size_t)r0 * N + col) = o1;
            *(float2*)(Cout + (size_t)(r0 + 8) * N + col) = o2;
        }
    }
    (void)row_l;
}

// ---------------------------------------------------------------------------
// Flash attention, fp32, causal. 64 queries x 64 keys per tile. (unchanged)
// ---------------------------------------------------------------------------
#define ATTN_SMEM_FLOATS (64 * 64 + 64 * 65 + 64 * 64 + 64 * 65)
#define ATTN_SMEM_BYTES  (ATTN_SMEM_FLOATS * 4)

__global__ __launch_bounds__(256) void flash_attn_kernel(
    const float* __restrict__ qkv, float* __restrict__ y)
{
    extern __shared__ float sm[];
    float* Qs = sm;                      // [64][64]
    float* Kt = Qs + 64 * 64;            // [64][65] (d, key)
    float* Vs = Kt + 64 * 65;            // [64][64]
    float* Ps = Vs + 64 * 64;            // [64][65]

    const int qi = blockIdx.x;
    const int h  = blockIdx.y;
    const int b  = blockIdx.z;
    const int tid = threadIdx.x;
    const int tx = tid & 15;
    const int ty = tid >> 4;
    const int q0 = qi * 64;
    const float scale = 0.125f;

    const float* base = qkv + (size_t)b * TT * 3 * CC;

#pragma unroll
    for (int it = 0; it < 4; it++) {
        int idx = it * 256 + tid;
        int row = idx >> 4;
        int c4  = (idx & 15) * 4;
        float4 v = *(const float4*)(base + (size_t)(q0 + row) * (3 * CC) + h * DD + c4);
        float4* dst = (float4*)&Qs[row * 64 + c4];
        dst->x = v.x * scale; dst->y = v.y * scale;
        dst->z = v.z * scale; dst->w = v.w * scale;
    }

    float m_i[4], l_i[4], acc[4][4];
#pragma unroll
    for (int i = 0; i < 4; i++) {
        m_i[i] = -1e30f; l_i[i] = 0.0f;
#pragma unroll
        for (int c = 0; c < 4; c++) acc[i][c] = 0.0f;
    }

    const int nkt = qi + 1;
    for (int kt = 0; kt < nkt; kt++) {
        const int k0 = kt * 64;
        __syncthreads();

#pragma unroll
        for (int it = 0; it < 4; it++) {
            int idx = it * 256 + tid;
            int row = idx >> 4;
            int c4  = (idx & 15) * 4;
            const float* kp = base + (size_t)(k0 + row) * (3 * CC) + CC + h * DD + c4;
            float4 kv = *(const float4*)kp;
            Kt[(c4 + 0) * 65 + row] = kv.x;
            Kt[(c4 + 1) * 65 + row] = kv.y;
            Kt[(c4 + 2) * 65 + row] = kv.z;
            Kt[(c4 + 3) * 65 + row] = kv.w;
            float4 vv = *(const float4*)(kp + CC);
            *(float4*)&Vs[row * 64 + c4] = vv;
        }
        __syncthreads();

        float s[4][4];
#pragma unroll
        for (int i = 0; i < 4; i++)
#pragma unroll
            for (int j = 0; j < 4; j++) s[i][j] = 0.0f;

#pragma unroll 8
        for (int d = 0; d < 64; d++) {
            float a[4], bv[4];
#pragma unroll
            for (int i = 0; i < 4; i++) a[i] = Qs[(ty * 4 + i) * 64 + d];
#pragma unroll
            for (int j = 0; j < 4; j++) bv[j] = Kt[d * 65 + tx * 4 + j];
#pragma unroll
            for (int i = 0; i < 4; i++)
#pragma unroll
                for (int j = 0; j < 4; j++)
                    s[i][j] = fmaf(a[i], bv[j], s[i][j]);
        }

        if (kt == qi) {
#pragma unroll
            for (int i = 0; i < 4; i++)
#pragma unroll
                for (int j = 0; j < 4; j++)
                    if (k0 + tx * 4 + j > q0 + ty * 4 + i) s[i][j] = -1e30f;
        }

#pragma unroll
        for (int i = 0; i < 4; i++) {
            float mloc = fmaxf(fmaxf(s[i][0], s[i][1]), fmaxf(s[i][2], s[i][3]));
#pragma unroll
            for (int o = 8; o >= 1; o >>= 1)
                mloc = fmaxf(mloc, __shfl_xor_sync(0xffffffffu, mloc, o, 16));
            float mnew = fmaxf(m_i[i], mloc);
            float alpha = __expf(m_i[i] - mnew);
            m_i[i] = mnew;
            float lloc = 0.0f;
#pragma unroll
            for (int j = 0; j < 4; j++) {
                float p = __expf(s[i][j] - mnew);
                s[i][j] = p;
                lloc += p;
            }
#pragma unroll
            for (int o = 8; o >= 1; o >>= 1)
                lloc += __shfl_xor_sync(0xffffffffu, lloc, o, 16);
            l_i[i] = l_i[i] * alpha + lloc;
#pragma unroll
            for (int c = 0; c < 4; c++) acc[i][c] *= alpha;
#pragma unroll
            for (int j = 0; j < 4; j++)
                Ps[(ty * 4 + i) * 65 + tx * 4 + j] = s[i][j];
        }
        __syncthreads();

#pragma unroll 8
        for (int j = 0; j < 64; j++) {
            float a[4];
#pragma unroll
            for (int i = 0; i < 4; i++) a[i] = Ps[(ty * 4 + i) * 65 + j];
            float4 bv = *(const float4*)&Vs[j * 64 + tx * 4];
#pragma unroll
            for (int i = 0; i < 4; i++) {
                acc[i][0] = fmaf(a[i], bv.x, acc[i][0]);
                acc[i][1] = fmaf(a[i], bv.y, acc[i][1]);
                acc[i][2] = fmaf(a[i], bv.z, acc[i][2]);
                acc[i][3] = fmaf(a[i], bv.w, acc[i][3]);
            }
        }
    }

#pragma unroll
    for (int i = 0; i < 4; i++) {
        float inv_l = 1.0f / l_i[i];
        float4 o;
        o.x = acc[i][0] * inv_l;
        o.y = acc[i][1] * inv_l;
        o.z = acc[i][2] * inv_l;
        o.w = acc[i][3] * inv_l;
        *(float4*)(y + (size_t)(b * TT + q0 + ty * 4 + i) * CC + h * DD + tx * 4) = o;
    }
}

// ---------------------------------------------------------------------------
// Launch
// ---------------------------------------------------------------------------
extern "C" void kernel_launch(void* const* d_in, const int* in_sizes, int n_in,
                              void* d_out, int out_size)
{
    const float* x  = (const float*)d_in[0];
    const float* We = (const float*)d_in[1];
    const float* be = (const float*)d_in[2];
    const float* Wp = (const float*)d_in[3];
    const float* bp = (const float*)d_in[4];
    float* out = (float*)d_out;

    float* qkv = nullptr;
    float* y = nullptr;
    cudaGetSymbolAddress((void**)&qkv, g_qkv);
    cudaGetSymbolAddress((void**)&y, g_y);

    static bool attr_done = false;
    if (!attr_done) {
        cudaFuncSetAttribute(flash_attn_kernel,
                             cudaFuncAttributeMaxDynamicSharedMemorySize,
                             ATTN_SMEM_BYTES);
        cudaFuncSetAttribute(gemm_nt_tf32,
                             cudaFuncAttributeMaxDynamicSharedMemorySize,
                             GEMM_SMEM_BYTES);
        attr_done = true;
    }

    const int M = BB * TT;   // 4096

    // 1) QKV = x @ We^T + be   (3xTF32 tensor-core GEMM)
    gemm_nt_tf32<<<dim3(3 * CC / 128, M / 128), 256, GEMM_SMEM_BYTES>>>(
        x, We, be, qkv, M, 3 * CC, CC);

    // 2) Flash attention (causal)
    flash_attn_kernel<<<dim3(TT / 64, HH, BB), 256, ATTN_SMEM_BYTES>>>(qkv, y);

    // 3) out = y @ Wp^T + bp
    gemm_nt_tf32<<<dim3(CC / 128, M / 128), 256, GEMM_SMEM_BYTES>>>(
        y, Wp, bp, out, M, CC, CC);
}

// round 3
// speedup vs baseline: 1.9877x; 1.6736x over previous
#include <cuda_runtime.h>
#include <cstdint>

// Problem constants
#define BB 2
#define TT 2048
#define CC 1024
#define HH 16
#define DD 64

// Scratch (device globals: allocation-free)
__device__ float g_qkv[BB * TT * 3 * CC];   // [B, T, 3C]
__device__ float g_y[BB * TT * CC];         // [B, T, C]

// ---------------------------------------------------------------------------
// helpers
// ---------------------------------------------------------------------------
__device__ __forceinline__ void cp_async16(uint32_t dst, const void* src) {
    asm volatile("cp.async.cg.shared.global [%0], [%1], 16;\n" :: "r"(dst), "l"(src));
}
__device__ __forceinline__ void cp_commit() { asm volatile("cp.async.commit_group;\n"); }
__device__ __forceinline__ void cp_wait0()  { asm volatile("cp.async.wait_group 0;\n"); }
__device__ __forceinline__ void cp_wait1()  { asm volatile("cp.async.wait_group 1;\n"); }

__device__ __forceinline__ void mma_tf32(float c[4],
    uint32_t a0, uint32_t a1, uint32_t a2, uint32_t a3,
    uint32_t b0, uint32_t b1)
{
    asm volatile(
        "mma.sync.aligned.m16n8k8.row.col.f32.tf32.tf32.f32 "
        "{%0,%1,%2,%3}, {%4,%5,%6,%7}, {%8,%9}, {%0,%1,%2,%3};\n"
        : "+f"(c[0]), "+f"(c[1]), "+f"(c[2]), "+f"(c[3])
        : "r"(a0), "r"(a1), "r"(a2), "r"(a3), "r"(b0), "r"(b1));
}

// Exact split: hi = tf32-truncated bits of x, lo = residual (exact in fp32).
__device__ __forceinline__ void tf32_split(float x, uint32_t& hi, uint32_t& lo) {
    uint32_t xb = __float_as_uint(x);
    hi = xb & 0xFFFFE000u;
    lo = __float_as_uint(x - __uint_as_float(hi));
}

// Round-to-nearest tf32 (unbiased single-pass operand)
__device__ __forceinline__ uint32_t f2tf32(float x) {
    uint32_t r;
    asm("cvt.rna.tf32.f32 %0, %1;" : "=r"(r) : "f"(x));
    return r;
}

// ---------------------------------------------------------------------------
// NT GEMM (2xTF32): Cout[m,n] = sum_k A[m,k]*W[n,k] + bias[n]
// A split hi/lo (exact), W rounded once. Block 128x128x32, 8 warps, 64x32/warp.
// ---------------------------------------------------------------------------
#define GPAD 36
#define GEMM_SMEM_BYTES (4 * 128 * GPAD * 4)

__global__ __launch_bounds__(256) void gemm_nt_tf32(
    const float* __restrict__ A, const float* __restrict__ W,
    const float* __restrict__ bias, float* __restrict__ Cout,
    int M, int N, int K)
{
    extern __shared__ float gsm[];
    float* As = gsm;                   // [2][128][GPAD]
    float* Bs = gsm + 2 * 128 * GPAD;  // [2][128][GPAD]

    const int tid  = threadIdx.x;
    const int wid  = tid >> 5;
    const int lane = tid & 31;
    const int g    = lane >> 2;
    const int cg   = lane & 3;
    const int wM   = wid >> 2;
    const int wN   = wid & 3;
    const int m0   = blockIdx.y * 128;
    const int n0   = blockIdx.x * 128;

    float acc[4][4][4];
#pragma unroll
    for (int mi = 0; mi < 4; mi++)
#pragma unroll
        for (int ni = 0; ni < 4; ni++)
#pragma unroll
            for (int r = 0; r < 4; r++) acc[mi][ni][r] = 0.0f;

    const int NT = K / 32;

    auto load_tile = [&](int kt, int buf) {
        const int k0 = kt * 32;
        float* dA = As + buf * 128 * GPAD;
        float* dB = Bs + buf * 128 * GPAD;
#pragma unroll
        for (int it = 0; it < 4; it++) {
            int idx = it * 256 + tid;
            int row = idx >> 3;
            int c4  = (idx & 7) * 4;
            cp_async16((uint32_t)__cvta_generic_to_shared(dA + row * GPAD + c4),
                       A + (size_t)(m0 + row) * K + k0 + c4);
            cp_async16((uint32_t)__cvta_generic_to_shared(dB + row * GPAD + c4),
                       W + (size_t)(n0 + row) * K + k0 + c4);
        }
    };

    load_tile(0, 0);
    cp_commit();

    for (int kt = 0; kt < NT; kt++) {
        cp_wait0();
        __syncthreads();
        if (kt + 1 < NT) {
            load_tile(kt + 1, (kt + 1) & 1);
            cp_commit();
        }

        const float* Ab = As + (kt & 1) * 128 * GPAD + (wM * 64) * GPAD;
        const float* Bb = Bs + (kt & 1) * 128 * GPAD + (wN * 32) * GPAD;

#pragma unroll
        for (int ks = 0; ks < 4; ks++) {
            uint32_t ahi[4][4], alo[4][4];
#pragma unroll
            for (int mi = 0; mi < 4; mi++) {
                const float* ap = Ab + (mi * 16 + g) * GPAD + ks * 8 + cg;
                tf32_split(ap[0],            ahi[mi][0], alo[mi][0]);
                tf32_split(ap[8 * GPAD],     ahi[mi][1], alo[mi][1]);
                tf32_split(ap[4],            ahi[mi][2], alo[mi][2]);
                tf32_split(ap[8 * GPAD + 4], ahi[mi][3], alo[mi][3]);
            }
#pragma unroll
            for (int ni = 0; ni < 4; ni++) {
                const float* bp = Bb + (ni * 8 + g) * GPAD + ks * 8 + cg;
                uint32_t b0 = f2tf32(bp[0]);
                uint32_t b1 = f2tf32(bp[4]);
#pragma unroll
                for (int mi = 0; mi < 4; mi++) {
                    mma_tf32(acc[mi][ni], ahi[mi][0], ahi[mi][1], ahi[mi][2], ahi[mi][3], b0, b1);
                    mma_tf32(acc[mi][ni], alo[mi][0], alo[mi][1], alo[mi][2], alo[mi][3], b0, b1);
                }
            }
        }
        __syncthreads();
    }

#pragma unroll
    for (int mi = 0; mi < 4; mi++) {
        int r0 = m0 + wM * 64 + mi * 16 + g;
#pragma unroll
        for (int ni = 0; ni < 4; ni++) {
            int col = n0 + wN * 32 + ni * 8 + 2 * cg;
            float b0v = bias[col], b1v = bias[col + 1];
            float2 o1 = { acc[mi][ni][0] + b0v, acc[mi][ni][1] + b1v };
            float2 o2 = { acc[mi][ni][2] + b0v, acc[mi][ni][3] + b1v };
            *(float2*)(Cout + (size_t)r0 * N + col) = o1;
            *(float2*)(Cout + (size_t)(r0 + 8) * N + col) = o2;
        }
    }
}

// ---------------------------------------------------------------------------
// Tensor-core flash attention (causal, base-2 online softmax).
// Block: 128 queries; 8 warps x 16 rows. Key tiles of 64, double-buffered.
// QK^T: 2-pass (Qhi+Qlo) x rna(K). PV: 1-pass rna(P) x rna(V).
// ---------------------------------------------------------------------------
#define KPAD 68
#define FA_SMEM_FLOATS (4 * 64 * KPAD + 128 * KPAD)
#define FA_SMEM_BYTES  (FA_SMEM_FLOATS * 4)

__global__ __launch_bounds__(256) void flash_attn_tf32(
    const float* __restrict__ qkv, float* __restrict__ y)
{
    extern __shared__ float sm[];
    float* Ks = sm;                      // [2][64][KPAD]  (key, d)
    float* Vs = sm + 2 * 64 * KPAD;      // [2][64][KPAD]  (key, d)
    float* Ps = sm + 4 * 64 * KPAD;      // [128][KPAD]    (Q staging, then P)

    const int qb = blockIdx.x;
    const int h  = blockIdx.y;
    const int b  = blockIdx.z;
    const int tid  = threadIdx.x;
    const int wid  = tid >> 5;
    const int lane = tid & 31;
    const int g    = lane >> 2;
    const int cg   = lane & 3;
    const int q0   = qb * 128;
    const float* base = qkv + (size_t)b * TT * 3 * CC;

    // Stage Q tile [128][64] into Ps (coalesced cp.async)
#pragma unroll
    for (int it = 0; it < 8; it++) {
        int idx = it * 256 + tid;
        int row = idx >> 4;
        int c4  = (idx & 15) * 4;
        cp_async16((uint32_t)__cvta_generic_to_shared(Ps + row * KPAD + c4),
                   base + (size_t)(q0 + row) * (3 * CC) + h * DD + c4);
    }
    cp_commit();

    const int nkt = 2 * qb + 2;

    // Preload K/V tile 0 while Q staging completes
    auto load_kv = [&](int kt, int buf) {
        const int k0 = kt * 64;
        float* dK = Ks + buf * 64 * KPAD;
        float* dV = Vs + buf * 64 * KPAD;
#pragma unroll
        for (int it = 0; it < 4; it++) {
            int idx = it * 256 + tid;
            int row = idx >> 4;
            int c4  = (idx & 15) * 4;
            const float* kp = base + (size_t)(k0 + row) * (3 * CC) + CC + h * DD + c4;
            cp_async16((uint32_t)__cvta_generic_to_shared(dK + row * KPAD + c4), kp);
            cp_async16((uint32_t)__cvta_generic_to_shared(dV + row * KPAD + c4), kp + CC);
        }
    };
    load_kv(0, 0);
    cp_commit();

    cp_wait1();             // Q staging group done (tile-0 group may be in flight)
    __syncthreads();

    // Q fragments (scale * log2(e) folded in), 2-pass split, kept in registers
    uint32_t qhi[8][4], qlo[8][4];
    {
        const float QS = 0.125f * 1.44269504089f;
        const float* Qw = Ps + (wid * 16 + g) * KPAD;
#pragma unroll
        for (int ks = 0; ks < 8; ks++) {
            tf32_split(Qw[ks * 8 + cg] * QS,            qhi[ks][0], qlo[ks][0]);
            tf32_split(Qw[8 * KPAD + ks * 8 + cg] * QS, qhi[ks][1], qlo[ks][1]);
            tf32_split(Qw[ks * 8 + cg + 4] * QS,        qhi[ks][2], qlo[ks][2]);
            tf32_split(Qw[8 * KPAD + ks * 8 + cg + 4] * QS, qhi[ks][3], qlo[ks][3]);
        }
    }
    __syncthreads();        // everyone done reading Q staging before P stores

    float m0 = -1e30f, m1 = -1e30f, l0 = 0.0f, l1 = 0.0f;
    float o[8][4];
#pragma unroll
    for (int ni = 0; ni < 8; ni++)
#pragma unroll
        for (int r = 0; r < 4; r++) o[ni][r] = 0.0f;

    for (int kt = 0; kt < nkt; kt++) {
        const int buf = kt & 1;
        __syncthreads();                 // prev PV done before overwriting buf^1
        if (kt + 1 < nkt) {
            load_kv(kt + 1, buf ^ 1);
            cp_commit();
            cp_wait1();
        } else {
            cp_wait0();
        }
        __syncthreads();                 // tile kt visible

        // S = Q K^T
        float sc[8][4];
#pragma unroll
        for (int ni = 0; ni < 8; ni++)
#pragma unroll
            for (int r = 0; r < 4; r++) sc[ni][r] = 0.0f;

        const float* Kb = Ks + buf * 64 * KPAD;
#pragma unroll
        for (int ks = 0; ks < 8; ks++) {
#pragma unroll
            for (int ni = 0; ni < 8; ni++) {
                const float* kp = Kb + (ni * 8 + g) * KPAD + ks * 8 + cg;
                uint32_t b0 = f2tf32(kp[0]);
                uint32_t b1 = f2tf32(kp[4]);
                mma_tf32(sc[ni], qhi[ks][0], qhi[ks][1], qhi[ks][2], qhi[ks][3], b0, b1);
                mma_tf32(sc[ni], qlo[ks][0], qlo[ks][1], qlo[ks][2], qlo[ks][3], b0, b1);
            }
        }

        // Causal mask (only the last two key tiles can cross the diagonal)
        if (kt >= nkt - 2) {
            int row0 = q0 + wid * 16 + g;
            int row1 = row0 + 8;
#pragma unroll
            for (int ni = 0; ni < 8; ni++) {
                int col = kt * 64 + ni * 8 + 2 * cg;
                if (col     > row0) sc[ni][0] = -1e30f;
                if (col + 1 > row0) sc[ni][1] = -1e30f;
                if (col     > row1) sc[ni][2] = -1e30f;
                if (col + 1 > row1) sc[ni][3] = -1e30f;
            }
        }

        // Online softmax (base 2), P -> smem
        float mx0 = -1e30f, mx1 = -1e30f;
#pragma unroll
        for (int ni = 0; ni < 8; ni++) {
            mx0 = fmaxf(mx0, fmaxf(sc[ni][0], sc[ni][1]));
            mx1 = fmaxf(mx1, fmaxf(sc[ni][2], sc[ni][3]));
        }
        mx0 = fmaxf(mx0, __shfl_xor_sync(0xffffffffu, mx0, 1));
        mx0 = fmaxf(mx0, __shfl_xor_sync(0xffffffffu, mx0, 2));
        mx1 = fmaxf(mx1, __shfl_xor_sync(0xffffffffu, mx1, 1));
        mx1 = fmaxf(mx1, __shfl_xor_sync(0xffffffffu, mx1, 2));

        float mn0 = fmaxf(m0, mx0), mn1 = fmaxf(m1, mx1);
        float al0 = exp2f(m0 - mn0), al1 = exp2f(m1 - mn1);
        m0 = mn0; m1 = mn1;

        float ls0 = 0.0f, ls1 = 0.0f;
        float* Pw = Ps + (wid * 16 + g) * KPAD;
#pragma unroll
        for (int ni = 0; ni < 8; ni++) {
            float p0 = exp2f(sc[ni][0] - mn0);
            float p1 = exp2f(sc[ni][1] - mn0);
            float p2 = exp2f(sc[ni][2] - mn1);
            float p3 = exp2f(sc[ni][3] - mn1);
            ls0 += p0 + p1;
            ls1 += p2 + p3;
            float2 w0 = {p0, p1}, w1 = {p2, p3};
            *(float2*)(Pw + ni * 8 + 2 * cg) = w0;
            *(float2*)(Pw + 8 * KPAD + ni * 8 + 2 * cg) = w1;
        }
        ls0 += __shfl_xor_sync(0xffffffffu, ls0, 1);
        ls0 += __shfl_xor_sync(0xffffffffu, ls0, 2);
        ls1 += __shfl_xor_sync(0xffffffffu, ls1, 1);
        ls1 += __shfl_xor_sync(0xffffffffu, ls1, 2);
        l0 = l0 * al0 + ls0;
        l1 = l1 * al1 + ls1;
#pragma unroll
        for (int ni = 0; ni < 8; ni++) {
            o[ni][0] *= al0; o[ni][1] *= al0;
            o[ni][2] *= al1; o[ni][3] *= al1;
        }
        __syncthreads();                 // P visible

        // O += P @ V
        const float* Vb = Vs + buf * 64 * KPAD;
#pragma unroll
        for (int ks = 0; ks < 8; ks++) {
            uint32_t a0 = f2tf32(Pw[ks * 8 + cg]);
            uint32_t a1 = f2tf32(Pw[8 * KPAD + ks * 8 + cg]);
            uint32_t a2 = f2tf32(Pw[ks * 8 + cg + 4]);
            uint32_t a3 = f2tf32(Pw[8 * KPAD + ks * 8 + cg + 4]);
#pragma unroll
            for (int ni = 0; ni < 8; ni++) {
                uint32_t b0 = f2tf32(Vb[(ks * 8 + cg) * KPAD + ni * 8 + g]);
                uint32_t b1 = f2tf32(Vb[(ks * 8 + cg + 4) * KPAD + ni * 8 + g]);
                mma_tf32(o[ni], a0, a1, a2, a3, b0, b1);
            }
        }
    }

    // Epilogue
    float il0 = 1.0f / l0, il1 = 1.0f / l1;
    int row0 = q0 + wid * 16 + g;
    float* yb = y + (size_t)b * TT * CC + (size_t)h * DD;
#pragma unroll
    for (int ni = 0; ni < 8; ni++) {
        int col = ni * 8 + 2 * cg;
        float2 w0 = {o[ni][0] * il0, o[ni][1] * il0};
        float2 w1 = {o[ni][2] * il1, o[ni][3] * il1};
        *(float2*)(yb + (size_t)row0 * CC + col) = w0;
        *(float2*)(yb + (size_t)(row0 + 8) * CC + col) = w1;
    }
}

// ---------------------------------------------------------------------------
// Launch
// ---------------------------------------------------------------------------
extern "C" void kernel_launch(void* const* d_in, const int* in_sizes, int n_in,
                              void* d_out, int out_size)
{
    const float* x  = (const float*)d_in[0];
    const float* We = (const float*)d_in[1];
    const float* be = (const float*)d_in[2];
    const float* Wp = (const float*)d_in[3];
    const float* bp = (const float*)d_in[4];
    float* out = (float*)d_out;

    float* qkv = nullptr;
    float* y = nullptr;
    cudaGetSymbolAddress((void**)&qkv, g_qkv);
    cudaGetSymbolAddress((void**)&y, g_y);

    static bool attr_done = false;
    if (!attr_done) {
        cudaFuncSetAttribute(gemm_nt_tf32,
                             cudaFuncAttributeMaxDynamicSharedMemorySize,
                             GEMM_SMEM_BYTES);
        cudaFuncSetAttribute(flash_attn_tf32,
                             cudaFuncAttributeMaxDynamicSharedMemorySize,
                             FA_SMEM_BYTES);
        attr_done = true;
    }

    const int M = BB * TT;   // 4096

    // 1) QKV = x @ We^T + be
    gemm_nt_tf32<<<dim3(3 * CC / 128, M / 128), 256, GEMM_SMEM_BYTES>>>(
        x, We, be, qkv, M, 3 * CC, CC);

    // 2) Flash attention (causal, tensor cores)
    flash_attn_tf32<<<dim3(TT / 128, HH, BB), 256, FA_SMEM_BYTES>>>(qkv, y);

    // 3) out = y @ Wp^T + bp
    gemm_nt_tf32<<<dim3(CC / 128, M / 128), 256, GEMM_SMEM_BYTES>>>(
        y, Wp, bp, out, M, CC, CC);
}

// round 5
// speedup vs baseline: 2.1657x; 1.0895x over previous
#include <cuda_runtime.h>
#include <cstdint>

// Problem constants
#define BB 2
#define TT 2048
#define CC 1024
#define HH 16
#define DD 64

// Scratch (device globals: allocation-free)
__device__ float g_qkv[BB * TT * 3 * CC];   // [B, T, 3C]
__device__ float g_y[BB * TT * CC];         // [B, T, C]

// ---------------------------------------------------------------------------
// helpers
// ---------------------------------------------------------------------------
__device__ __forceinline__ void cp_async16(uint32_t dst, const void* src) {
    asm volatile("cp.async.cg.shared.global [%0], [%1], 16;\n" :: "r"(dst), "l"(src));
}
__device__ __forceinline__ void cp_commit() { asm volatile("cp.async.commit_group;\n"); }
__device__ __forceinline__ void cp_wait0()  { asm volatile("cp.async.wait_group 0;\n"); }
__device__ __forceinline__ void cp_wait1()  { asm volatile("cp.async.wait_group 1;\n"); }

__device__ __forceinline__ void mma_tf32(float c[4],
    uint32_t a0, uint32_t a1, uint32_t a2, uint32_t a3,
    uint32_t b0, uint32_t b1)
{
    asm volatile(
        "mma.sync.aligned.m16n8k8.row.col.f32.tf32.tf32.f32 "
        "{%0,%1,%2,%3}, {%4,%5,%6,%7}, {%8,%9}, {%0,%1,%2,%3};\n"
        : "+f"(c[0]), "+f"(c[1]), "+f"(c[2]), "+f"(c[3])
        : "r"(a0), "r"(a1), "r"(a2), "r"(a3), "r"(b0), "r"(b1));
}

// Exact split: hi = tf32-truncated bits of x, lo = residual (exact in fp32).
__device__ __forceinline__ void tf32_split(float x, uint32_t& hi, uint32_t& lo) {
    uint32_t xb = __float_as_uint(x);
    hi = xb & 0xFFFFE000u;
    lo = __float_as_uint(x - __uint_as_float(hi));
}

// Round-to-nearest tf32 (unbiased single-pass operand)
__device__ __forceinline__ uint32_t f2tf32(float x) {
    uint32_t r;
    asm("cvt.rna.tf32.f32 %0, %1;" : "=r"(r) : "f"(x));
    return r;
}

// ---------------------------------------------------------------------------
// NT GEMM (2xTF32): Cout[m,n] = sum_k A[m,k]*W[n,k] + bias[n]
// A split hi/lo (exact), W rounded once. Block 128x128x32, 8 warps, 64x32/warp.
// __launch_bounds__(256, 2): force 2 CTAs/SM (regs capped at 128).
// ---------------------------------------------------------------------------
#define GPAD 36
#define GEMM_SMEM_BYTES (4 * 128 * GPAD * 4)

__global__ __launch_bounds__(256, 2) void gemm_nt_tf32(
    const float* __restrict__ A, const float* __restrict__ W,
    const float* __restrict__ bias, float* __restrict__ Cout,
    int M, int N, int K)
{
    extern __shared__ float gsm[];
    float* As = gsm;                   // [2][128][GPAD]
    float* Bs = gsm + 2 * 128 * GPAD;  // [2][128][GPAD]

    const int tid  = threadIdx.x;
    const int wid  = tid >> 5;
    const int lane = tid & 31;
    const int g    = lane >> 2;
    const int cg   = lane & 3;
    const int wM   = wid >> 2;
    const int wN   = wid & 3;
    const int m0   = blockIdx.y * 128;
    const int n0   = blockIdx.x * 128;

    float acc[4][4][4];
#pragma unroll
    for (int mi = 0; mi < 4; mi++)
#pragma unroll
        for (int ni = 0; ni < 4; ni++)
#pragma unroll
            for (int r = 0; r < 4; r++) acc[mi][ni][r] = 0.0f;

    const int NT = K / 32;

    auto load_tile = [&](int kt, int buf) {
        const int k0 = kt * 32;
        float* dA = As + buf * 128 * GPAD;
        float* dB = Bs + buf * 128 * GPAD;
#pragma unroll
        for (int it = 0; it < 4; it++) {
            int idx = it * 256 + tid;
            int row = idx >> 3;
            int c4  = (idx & 7) * 4;
            cp_async16((uint32_t)__cvta_generic_to_shared(dA + row * GPAD + c4),
                       A + (size_t)(m0 + row) * K + k0 + c4);
            cp_async16((uint32_t)__cvta_generic_to_shared(dB + row * GPAD + c4),
                       W + (size_t)(n0 + row) * K + k0 + c4);
        }
    };

    load_tile(0, 0);
    cp_commit();

    for (int kt = 0; kt < NT; kt++) {
        cp_wait0();
        __syncthreads();
        if (kt + 1 < NT) {
            load_tile(kt + 1, (kt + 1) & 1);
            cp_commit();
        }

        const float* Ab = As + (kt & 1) * 128 * GPAD + (wM * 64) * GPAD;
        const float* Bb = Bs + (kt & 1) * 128 * GPAD + (wN * 32) * GPAD;

#pragma unroll
        for (int ks = 0; ks < 4; ks++) {
            uint32_t ahi[4][4], alo[4][4];
#pragma unroll
            for (int mi = 0; mi < 4; mi++) {
                const float* ap = Ab + (mi * 16 + g) * GPAD + ks * 8 + cg;
                tf32_split(ap[0],            ahi[mi][0], alo[mi][0]);
                tf32_split(ap[8 * GPAD],     ahi[mi][1], alo[mi][1]);
                tf32_split(ap[4],            ahi[mi][2], alo[mi][2]);
                tf32_split(ap[8 * GPAD + 4], ahi[mi][3], alo[mi][3]);
            }
#pragma unroll
            for (int ni = 0; ni < 4; ni++) {
                const float* bp = Bb + (ni * 8 + g) * GPAD + ks * 8 + cg;
                uint32_t b0 = f2tf32(bp[0]);
                uint32_t b1 = f2tf32(bp[4]);
#pragma unroll
                for (int mi = 0; mi < 4; mi++) {
                    mma_tf32(acc[mi][ni], ahi[mi][0], ahi[mi][1], ahi[mi][2], ahi[mi][3], b0, b1);
                    mma_tf32(acc[mi][ni], alo[mi][0], alo[mi][1], alo[mi][2], alo[mi][3], b0, b1);
                }
            }
        }
        __syncthreads();
    }

#pragma unroll
    for (int mi = 0; mi < 4; mi++) {
        int r0 = m0 + wM * 64 + mi * 16 + g;
#pragma unroll
        for (int ni = 0; ni < 4; ni++) {
            int col = n0 + wN * 32 + ni * 8 + 2 * cg;
            float b0v = bias[col], b1v = bias[col + 1];
            float2 o1 = { acc[mi][ni][0] + b0v, acc[mi][ni][1] + b1v };
            float2 o2 = { acc[mi][ni][2] + b0v, acc[mi][ni][3] + b1v };
            *(float2*)(Cout + (size_t)r0 * N + col) = o1;
            *(float2*)(Cout + (size_t)(r0 + 8) * N + col) = o2;
        }
    }
}

// ---------------------------------------------------------------------------
// Tensor-core flash attention (causal, base-2 online softmax).
// Block: 128 queries; 8 warps x 16 rows. Key tiles of 64, double-buffered.
// QK^T: 2-pass (Qhi+Qlo) x rna(K). PV: 1-pass rna(P) x rna(V).
// Heavy query tiles scheduled first (reversed bid) for causal load balance.
// ---------------------------------------------------------------------------
#define KPAD 68
#define FA_SMEM_FLOATS (4 * 64 * KPAD + 128 * KPAD)
#define FA_SMEM_BYTES  (FA_SMEM_FLOATS * 4)

__global__ __launch_bounds__(256) void flash_attn_tf32(
    const float* __restrict__ qkv, float* __restrict__ y)
{
    extern __shared__ float sm[];
    float* Ks = sm;                      // [2][64][KPAD]
    float* Vs = sm + 2 * 64 * KPAD;      // [2][64][KPAD]
    float* Ps = sm + 4 * 64 * KPAD;      // [128][KPAD]

    const int qb = (gridDim.x - 1) - blockIdx.x;   // heavy tiles first
    const int h  = blockIdx.y;
    const int b  = blockIdx.z;
    const int tid  = threadIdx.x;
    const int wid  = tid >> 5;
    const int lane = tid & 31;
    const int g    = lane >> 2;
    const int cg   = lane & 3;
    const int q0   = qb * 128;
    const float* base = qkv + (size_t)b * TT * 3 * CC;

#pragma unroll
    for (int it = 0; it < 8; it++) {
        int idx = it * 256 + tid;
        int row = idx >> 4;
        int c4  = (idx & 15) * 4;
        cp_async16((uint32_t)__cvta_generic_to_shared(Ps + row * KPAD + c4),
                   base + (size_t)(q0 + row) * (3 * CC) + h * DD + c4);
    }
    cp_commit();

    const int nkt = 2 * qb + 2;

    auto load_kv = [&](int kt, int buf) {
        const int k0 = kt * 64;
        float* dK = Ks + buf * 64 * KPAD;
        float* dV = Vs + buf * 64 * KPAD;
#pragma unroll
        for (int it = 0; it < 4; it++) {
            int idx = it * 256 + tid;
            int row = idx >> 4;
            int c4  = (idx & 15) * 4;
            const float* kp = base + (size_t)(k0 + row) * (3 * CC) + CC + h * DD + c4;
            cp_async16((uint32_t)__cvta_generic_to_shared(dK + row * KPAD + c4), kp);
            cp_async16((uint32_t)__cvta_generic_to_shared(dV + row * KPAD + c4), kp + CC);
        }
    };
    load_kv(0, 0);
    cp_commit();

    cp_wait1();             // Q staging group done
    __syncthreads();

    uint32_t qhi[8][4], qlo[8][4];
    {
        const float QS = 0.125f * 1.44269504089f;
        const float* Qw = Ps + (wid * 16 + g) * KPAD;
#pragma unroll
        for (int ks = 0; ks < 8; ks++) {
            tf32_split(Qw[ks * 8 + cg] * QS,                qhi[ks][0], qlo[ks][0]);
            tf32_split(Qw[8 * KPAD + ks * 8 + cg] * QS,     qhi[ks][1], qlo[ks][1]);
            tf32_split(Qw[ks * 8 + cg + 4] * QS,            qhi[ks][2], qlo[ks][2]);
            tf32_split(Qw[8 * KPAD + ks * 8 + cg + 4] * QS, qhi[ks][3], qlo[ks][3]);
        }
    }
    __syncthreads();        // everyone done reading Q staging before P stores

    float m0 = -1e30f, m1 = -1e30f, l0 = 0.0f, l1 = 0.0f;
    float o[8][4];
#pragma unroll
    for (int ni = 0; ni < 8; ni++)
#pragma unroll
        for (int r = 0; r < 4; r++) o[ni][r] = 0.0f;

    for (int kt = 0; kt < nkt; kt++) {
        const int buf = kt & 1;
        __syncthreads();                 // prev PV done before overwriting buf^1
        if (kt + 1 < nkt) {
            load_kv(kt + 1, buf ^ 1);
            cp_commit();
            cp_wait1();
        } else {
            cp_wait0();
        }
        __syncthreads();                 // tile kt visible

        float sc[8][4];
#pragma unroll
        for (int ni = 0; ni < 8; ni++)
#pragma unroll
            for (int r = 0; r < 4; r++) sc[ni][r] = 0.0f;

        const float* Kb = Ks + buf * 64 * KPAD;
#pragma unroll
        for (int ks = 0; ks < 8; ks++) {
#pragma unroll
            for (int ni = 0; ni < 8; ni++) {
                const float* kp = Kb + (ni * 8 + g) * KPAD + ks * 8 + cg;
                uint32_t b0 = f2tf32(kp[0]);
                uint32_t b1 = f2tf32(kp[4]);
                mma_tf32(sc[ni], qhi[ks][0], qhi[ks][1], qhi[ks][2], qhi[ks][3], b0, b1);
                mma_tf32(sc[ni], qlo[ks][0], qlo[ks][1], qlo[ks][2], qlo[ks][3], b0, b1);
            }
        }

        if (kt >= nkt - 2) {
            int row0 = q0 + wid * 16 + g;
            int row1 = row0 + 8;
#pragma unroll
            for (int ni = 0; ni < 8; ni++) {
                int col = kt * 64 + ni * 8 + 2 * cg;
                if (col     > row0) sc[ni][0] = -1e30f;
                if (col + 1 > row0) sc[ni][1] = -1e30f;
                if (col     > row1) sc[ni][2] = -1e30f;
                if (col + 1 > row1) sc[ni][3] = -1e30f;
            }
        }

        float mx0 = -1e30f, mx1 = -1e30f;
#pragma unroll
        for (int ni = 0; ni < 8; ni++) {
            mx0 = fmaxf(mx0, fmaxf(sc[ni][0], sc[ni][1]));
            mx1 = fmaxf(mx1, fmaxf(sc[ni][2], sc[ni][3]));
        }
        mx0 = fmaxf(mx0, __shfl_xor_sync(0xffffffffu, mx0, 1));
        mx0 = fmaxf(mx0, __shfl_xor_sync(0xffffffffu, mx0, 2));
        mx1 = fmaxf(mx1, __shfl_xor_sync(0xffffffffu, mx1, 1));
        mx1 = fmaxf(mx1, __shfl_xor_sync(0xffffffffu, mx1, 2));

        float mn0 = fmaxf(m0, mx0), mn1 = fmaxf(m1, mx1);
        float al0 = exp2f(m0 - mn0), al1 = exp2f(m1 - mn1);
        m0 = mn0; m1 = mn1;

        float ls0 = 0.0f, ls1 = 0.0f;
        float* Pw = Ps + (wid * 16 + g) * KPAD;
#pragma unroll
        for (int ni = 0; ni < 8; ni++) {
            float p0 = exp2f(sc[ni][0] - mn0);
            float p1 = exp2f(sc[ni][1] - mn0);
            float p2 = exp2f(sc[ni][2] - mn1);
            float p3 = exp2f(sc[ni][3] - mn1);
            ls0 += p0 + p1;
            ls1 += p2 + p3;
            float2 w0 = {p0, p1}, w1 = {p2, p3};
            *(float2*)(Pw + ni * 8 + 2 * cg) = w0;
            *(float2*)(Pw + 8 * KPAD + ni * 8 + 2 * cg) = w1;
        }
        ls0 += __shfl_xor_sync(0xffffffffu, ls0, 1);
        ls0 += __shfl_xor_sync(0xffffffffu, ls0, 2);
        ls1 += __shfl_xor_sync(0xffffffffu, ls1, 1);
        ls1 += __shfl_xor_sync(0xffffffffu, ls1, 2);
        l0 = l0 * al0 + ls0;
        l1 = l1 * al1 + ls1;
#pragma unroll
        for (int ni = 0; ni < 8; ni++) {
            o[ni][0] *= al0; o[ni][1] *= al0;
            o[ni][2] *= al1; o[ni][3] *= al1;
        }
        __syncthreads();                 // P visible

        const float* Vb = Vs + buf * 64 * KPAD;
#pragma unroll
        for (int ks = 0; ks < 8; ks++) {
            uint32_t a0 = f2tf32(Pw[ks * 8 + cg]);
            uint32_t a1 = f2tf32(Pw[8 * KPAD + ks * 8 + cg]);
            uint32_t a2 = f2tf32(Pw[ks * 8 + cg + 4]);
            uint32_t a3 = f2tf32(Pw[8 * KPAD + ks * 8 + cg + 4]);
#pragma unroll
            for (int ni = 0; ni < 8; ni++) {
                uint32_t b0 = f2tf32(Vb[(ks * 8 + cg) * KPAD + ni * 8 + g]);
                uint32_t b1 = f2tf32(Vb[(ks * 8 + cg + 4) * KPAD + ni * 8 + g]);
                mma_tf32(o[ni], a0, a1, a2, a3, b0, b1);
            }
        }
    }

    float il0 = 1.0f / l0, il1 = 1.0f / l1;
    int row0 = q0 + wid * 16 + g;
    float* yb = y + (size_t)b * TT * CC + (size_t)h * DD;
#pragma unroll
    for (int ni = 0; ni < 8; ni++) {
        int col = ni * 8 + 2 * cg;
        float2 w0 = {o[ni][0] * il0, o[ni][1] * il0};
        float2 w1 = {o[ni][2] * il1, o[ni][3] * il1};
        *(float2*)(yb + (size_t)row0 * CC + col) = w0;
        *(float2*)(yb + (size_t)(row0 + 8) * CC + col) = w1;
    }
}

// ---------------------------------------------------------------------------
// Launch
// ---------------------------------------------------------------------------
extern "C" void kernel_launch(void* const* d_in, const int* in_sizes, int n_in,
                              void* d_out, int out_size)
{
    const float* x  = (const float*)d_in[0];
    const float* We = (const float*)d_in[1];
    const float* be = (const float*)d_in[2];
    const float* Wp = (const float*)d_in[3];
    const float* bp = (const float*)d_in[4];
    float* out = (float*)d_out;

    float* qkv = nullptr;
    float* y = nullptr;
    cudaGetSymbolAddress((void**)&qkv, g_qkv);
    cudaGetSymbolAddress((void**)&y, g_y);

    static bool attr_done = false;
    if (!attr_done) {
        cudaFuncSetAttribute(gemm_nt_tf32,
                             cudaFuncAttributeMaxDynamicSharedMemorySize,
                             GEMM_SMEM_BYTES);
        cudaFuncSetAttribute(flash_attn_tf32,
                             cudaFuncAttributeMaxDynamicSharedMemorySize,
                             FA_SMEM_BYTES);
        attr_done = true;
    }

    const int M = BB * TT;   // 4096

    // 1) QKV = x @ We^T + be
    gemm_nt_tf32<<<dim3(3 * CC / 128, M / 128), 256, GEMM_SMEM_BYTES>>>(
        x, We, be, qkv, M, 3 * CC, CC);

    // 2) Flash attention (causal, tensor cores)
    flash_attn_tf32<<<dim3(TT / 128, HH, BB), 256, FA_SMEM_BYTES>>>(qkv, y);

    // 3) out = y @ Wp^T + bp
    gemm_nt_tf32<<<dim3(CC / 128, M / 128), 256, GEMM_SMEM_BYTES>>>(
        y, Wp, bp, out, M, CC, CC);
}

// round 6
// speedup vs baseline: 2.3305x; 1.0761x over previous
#include <cuda_runtime.h>
#include <cstdint>

// Problem constants
#define BB 2
#define TT 2048
#define CC 1024
#define HH 16
#define DD 64

// Scratch (device globals: allocation-free)
__device__ float g_qkv[BB * TT * 3 * CC];   // [B, T, 3C]
__device__ float g_y[BB * TT * CC];         // [B, T, C]

// ---------------------------------------------------------------------------
// helpers
// ---------------------------------------------------------------------------
__device__ __forceinline__ void cp_async16(uint32_t dst, const void* src) {
    asm volatile("cp.async.cg.shared.global [%0], [%1], 16;\n" :: "r"(dst), "l"(src));
}
__device__ __forceinline__ void cp_commit() { asm volatile("cp.async.commit_group;\n"); }
__device__ __forceinline__ void cp_wait0()  { asm volatile("cp.async.wait_group 0;\n"); }
__device__ __forceinline__ void cp_wait1()  { asm volatile("cp.async.wait_group 1;\n"); }

__device__ __forceinline__ void mma_tf32(float c[4],
    uint32_t a0, uint32_t a1, uint32_t a2, uint32_t a3,
    uint32_t b0, uint32_t b1)
{
    asm volatile(
        "mma.sync.aligned.m16n8k8.row.col.f32.tf32.tf32.f32 "
        "{%0,%1,%2,%3}, {%4,%5,%6,%7}, {%8,%9}, {%0,%1,%2,%3};\n"
        : "+f"(c[0]), "+f"(c[1]), "+f"(c[2]), "+f"(c[3])
        : "r"(a0), "r"(a1), "r"(a2), "r"(a3), "r"(b0), "r"(b1));
}

__device__ __forceinline__ void mma_bf16(float c[4],
    uint32_t a0, uint32_t a1, uint32_t a2, uint32_t a3,
    uint32_t b0, uint32_t b1)
{
    asm volatile(
        "mma.sync.aligned.m16n8k16.row.col.f32.bf16.bf16.f32 "
        "{%0,%1,%2,%3}, {%4,%5,%6,%7}, {%8,%9}, {%0,%1,%2,%3};\n"
        : "+f"(c[0]), "+f"(c[1]), "+f"(c[2]), "+f"(c[3])
        : "r"(a0), "r"(a1), "r"(a2), "r"(a3), "r"(b0), "r"(b1));
}

__device__ __forceinline__ void ldm4(uint32_t r[4], uint32_t addr) {
    asm volatile("ldmatrix.sync.aligned.m8n8.x4.shared.b16 {%0,%1,%2,%3}, [%4];"
                 : "=r"(r[0]), "=r"(r[1]), "=r"(r[2]), "=r"(r[3]) : "r"(addr));
}

// Exact split: hi = tf32-truncated bits of x, lo = residual (exact in fp32).
__device__ __forceinline__ void tf32_split(float x, uint32_t& hi, uint32_t& lo) {
    uint32_t xb = __float_as_uint(x);
    hi = xb & 0xFFFFE000u;
    lo = __float_as_uint(x - __uint_as_float(hi));
}

__device__ __forceinline__ uint32_t f2tf32(float x) {
    uint32_t r;
    asm("cvt.rna.tf32.f32 %0, %1;" : "=r"(r) : "f"(x));
    return r;
}

// Split float4 into bf16 hi (rn) + bf16 lo (rn of residual), packed pairwise.
// Low 16 bits of each u32 = lower-k element (memory order).
__device__ __forceinline__ void bsplit(float4 v, uint2& h, uint2& l) {
    uint32_t h01, h23;
    asm("cvt.rn.bf16x2.f32 %0, %1, %2;" : "=r"(h01) : "f"(v.y), "f"(v.x));
    asm("cvt.rn.bf16x2.f32 %0, %1, %2;" : "=r"(h23) : "f"(v.w), "f"(v.z));
    float lx = v.x - __uint_as_float(h01 << 16);
    float ly = v.y - __uint_as_float(h01 & 0xFFFF0000u);
    float lz = v.z - __uint_as_float(h23 << 16);
    float lw = v.w - __uint_as_float(h23 & 0xFFFF0000u);
    uint32_t l01, l23;
    asm("cvt.rn.bf16x2.f32 %0, %1, %2;" : "=r"(l01) : "f"(ly), "f"(lx));
    asm("cvt.rn.bf16x2.f32 %0, %1, %2;" : "=r"(l23) : "f"(lw), "f"(lz));
    h = make_uint2(h01, h23);
    l = make_uint2(l01, l23);
}

// ---------------------------------------------------------------------------
// NT GEMM (3x bf16, m16n8k16): Cout[m,n] = sum_k A[m,k]*W[n,k] + bias[n]
// Block 128x128x32, 8 warps (2x4), warp tile 64x32.
// smem: double-buffered pre-split bf16 tiles (A_hi, A_lo, B_hi, B_lo),
// row stride 80 bytes -> conflict-free ldmatrix phases.
// ---------------------------------------------------------------------------
#define GSTRIDE 80                     // bytes per 32-k bf16 row
#define TILE_B (128 * GSTRIDE)         // 10240 per tile
#define BUF_B  (4 * TILE_B)            // 40960 per buffer
#define GEMM_SMEM_BYTES (2 * BUF_B)    // 81920

__global__ __launch_bounds__(256, 2) void gemm_bf16x3(
    const float* __restrict__ A, const float* __restrict__ W,
    const float* __restrict__ bias, float* __restrict__ Cout,
    int M, int N, int K)
{
    extern __shared__ char smg[];
    const uint32_t sb = (uint32_t)__cvta_generic_to_shared(smg);
    const int tid  = threadIdx.x;
    const int wid  = tid >> 5;
    const int lane = tid & 31;
    const int g    = lane >> 2;
    const int cg   = lane & 3;
    const int wM   = wid >> 2;
    const int wN   = wid & 3;
    const int m0   = blockIdx.y * 128;
    const int n0   = blockIdx.x * 128;

    // ldmatrix per-lane byte offsets within a tile
    const uint32_t aoff = (uint32_t)(wM * 64 + (lane & 15)) * GSTRIDE + ((lane >> 4) * 16);
    const uint32_t boff = (uint32_t)(wN * 32 + ((lane & 16) >> 1) + (lane & 7)) * GSTRIDE
                        + ((lane & 8) * 2);

    float acc[4][4][4];
#pragma unroll
    for (int mi = 0; mi < 4; mi++)
#pragma unroll
        for (int ni = 0; ni < 4; ni++)
#pragma unroll
            for (int r = 0; r < 4; r++) acc[mi][ni][r] = 0.0f;

    const int NC = K / 32;
    float4 av[4], bv[4];

    auto load_regs = [&](int kc) {
        const int k0 = kc * 32;
#pragma unroll
        for (int i = 0; i < 4; i++) {
            int idx = i * 256 + tid, row = idx >> 3, c4 = (idx & 7) * 4;
            av[i] = *(const float4*)(A + (size_t)(m0 + row) * K + k0 + c4);
            bv[i] = *(const float4*)(W + (size_t)(n0 + row) * K + k0 + c4);
        }
    };
    auto sts_regs = [&](uint32_t bufoff) {
#pragma unroll
        for (int i = 0; i < 4; i++) {
            int idx = i * 256 + tid, row = idx >> 3, c4 = (idx & 7) * 4;
            uint32_t bo = (uint32_t)row * GSTRIDE + c4 * 2;
            uint2 h, l;
            bsplit(av[i], h, l);
            *(uint2*)(smg + bufoff + 0 * TILE_B + bo) = h;
            *(uint2*)(smg + bufoff + 1 * TILE_B + bo) = l;
            bsplit(bv[i], h, l);
            *(uint2*)(smg + bufoff + 2 * TILE_B + bo) = h;
            *(uint2*)(smg + bufoff + 3 * TILE_B + bo) = l;
        }
    };

    // Pipeline priming: chunk 0 -> buf0, chunk 1 -> regs
    load_regs(0);
    sts_regs(0);
    __syncthreads();
    if (NC > 1) load_regs(1);

    for (int kc = 0; kc < NC; kc++) {
        const uint32_t bufo = (uint32_t)(kc & 1) * BUF_B;
        if (kc + 1 < NC) {
            sts_regs(bufo ^ BUF_B);            // chunk kc+1 -> other buffer
            if (kc + 2 < NC) load_regs(kc + 2);
        }

        const uint32_t ahB = sb + bufo + 0 * TILE_B + aoff;
        const uint32_t alB = sb + bufo + 1 * TILE_B + aoff;
        const uint32_t bhB = sb + bufo + 2 * TILE_B + boff;
        const uint32_t blB = sb + bufo + 3 * TILE_B + boff;

#pragma unroll
        for (int s = 0; s < 2; s++) {          // two k16 steps per 32-k chunk
            uint32_t ah[4][4], al[4][4], bh[2][4], bl[2][4];
#pragma unroll
            for (int mi = 0; mi < 4; mi++) {
                ldm4(ah[mi], ahB + mi * (16 * GSTRIDE) + s * 32);
                ldm4(al[mi], alB + mi * (16 * GSTRIDE) + s * 32);
            }
#pragma unroll
            for (int p = 0; p < 2; p++) {
                ldm4(bh[p], bhB + p * (16 * GSTRIDE) + s * 32);
                ldm4(bl[p], blB + p * (16 * GSTRIDE) + s * 32);
            }
#pragma unroll
            for (int mi = 0; mi < 4; mi++)
#pragma unroll
                for (int ni = 0; ni < 4; ni++) {
                    const int p = ni >> 1, hf = (ni & 1) * 2;
                    mma_bf16(acc[mi][ni], ah[mi][0], ah[mi][1], ah[mi][2], ah[mi][3],
                             bh[p][hf], bh[p][hf + 1]);
                    mma_bf16(acc[mi][ni], al[mi][0], al[mi][1], al[mi][2], al[mi][3],
                             bh[p][hf], bh[p][hf + 1]);
                    mma_bf16(acc[mi][ni], ah[mi][0], ah[mi][1], ah[mi][2], ah[mi][3],
                             bl[p][hf], bl[p][hf + 1]);
                }
        }
        __syncthreads();
    }

    // Epilogue with bias
#pragma unroll
    for (int mi = 0; mi < 4; mi++) {
        int r0 = m0 + wM * 64 + mi * 16 + g;
#pragma unroll
        for (int ni = 0; ni < 4; ni++) {
            int col = n0 + wN * 32 + ni * 8 + 2 * cg;
            float b0v = bias[col], b1v = bias[col + 1];
            float2 o1 = { acc[mi][ni][0] + b0v, acc[mi][ni][1] + b1v };
            float2 o2 = { acc[mi][ni][2] + b0v, acc[mi][ni][3] + b1v };
            *(float2*)(Cout + (size_t)r0 * N + col) = o1;
            *(float2*)(Cout + (size_t)(r0 + 8) * N + col) = o2;
        }
    }
}

// ---------------------------------------------------------------------------
// Tensor-core flash attention (causal, base-2 online softmax). Unchanged.
// Block: 128 queries; 8 warps x 16 rows. Key tiles of 64, double-buffered.
// QK^T: 2-pass (Qhi+Qlo) x rna(K). PV: 1-pass rna(P) x rna(V).
// ---------------------------------------------------------------------------
#define KPAD 68
#define FA_SMEM_FLOATS (4 * 64 * KPAD + 128 * KPAD)
#define FA_SMEM_BYTES  (FA_SMEM_FLOATS * 4)

__global__ __launch_bounds__(256) void flash_attn_tf32(
    const float* __restrict__ qkv, float* __restrict__ y)
{
    extern __shared__ float sm[];
    float* Ks = sm;                      // [2][64][KPAD]
    float* Vs = sm + 2 * 64 * KPAD;      // [2][64][KPAD]
    float* Ps = sm + 4 * 64 * KPAD;      // [128][KPAD]

    const int qb = (gridDim.x - 1) - blockIdx.x;   // heavy tiles first
    const int h  = blockIdx.y;
    const int b  = blockIdx.z;
    const int tid  = threadIdx.x;
    const int wid  = tid >> 5;
    const int lane = tid & 31;
    const int g    = lane >> 2;
    const int cg   = lane & 3;
    const int q0   = qb * 128;
    const float* base = qkv + (size_t)b * TT * 3 * CC;

#pragma unroll
    for (int it = 0; it < 8; it++) {
        int idx = it * 256 + tid;
        int row = idx >> 4;
        int c4  = (idx & 15) * 4;
        cp_async16((uint32_t)__cvta_generic_to_shared(Ps + row * KPAD + c4),
                   base + (size_t)(q0 + row) * (3 * CC) + h * DD + c4);
    }
    cp_commit();

    const int nkt = 2 * qb + 2;

    auto load_kv = [&](int kt, int buf) {
        const int k0 = kt * 64;
        float* dK = Ks + buf * 64 * KPAD;
        float* dV = Vs + buf * 64 * KPAD;
#pragma unroll
        for (int it = 0; it < 4; it++) {
            int idx = it * 256 + tid;
            int row = idx >> 4;
            int c4  = (idx & 15) * 4;
            const float* kp = base + (size_t)(k0 + row) * (3 * CC) + CC + h * DD + c4;
            cp_async16((uint32_t)__cvta_generic_to_shared(dK + row * KPAD + c4), kp);
            cp_async16((uint32_t)__cvta_generic_to_shared(dV + row * KPAD + c4), kp + CC);
        }
    };
    load_kv(0, 0);
    cp_commit();

    cp_wait1();
    __syncthreads();

    uint32_t qhi[8][4], qlo[8][4];
    {
        const float QS = 0.125f * 1.44269504089f;
        const float* Qw = Ps + (wid * 16 + g) * KPAD;
#pragma unroll
        for (int ks = 0; ks < 8; ks++) {
            tf32_split(Qw[ks * 8 + cg] * QS,                qhi[ks][0], qlo[ks][0]);
            tf32_split(Qw[8 * KPAD + ks * 8 + cg] * QS,     qhi[ks][1], qlo[ks][1]);
            tf32_split(Qw[ks * 8 + cg + 4] * QS,            qhi[ks][2], qlo[ks][2]);
            tf32_split(Qw[8 * KPAD + ks * 8 + cg + 4] * QS, qhi[ks][3], qlo[ks][3]);
        }
    }
    __syncthreads();

    float m0 = -1e30f, m1 = -1e30f, l0 = 0.0f, l1 = 0.0f;
    float o[8][4];
#pragma unroll
    for (int ni = 0; ni < 8; ni++)
#pragma unroll
        for (int r = 0; r < 4; r++) o[ni][r] = 0.0f;

    for (int kt = 0; kt < nkt; kt++) {
        const int buf = kt & 1;
        __syncthreads();
        if (kt + 1 < nkt) {
            load_kv(kt + 1, buf ^ 1);
            cp_commit();
            cp_wait1();
        } else {
            cp_wait0();
        }
        __syncthreads();

        float sc[8][4];
#pragma unroll
        for (int ni = 0; ni < 8; ni++)
#pragma unroll
            for (int r = 0; r < 4; r++) sc[ni][r] = 0.0f;

        const float* Kb = Ks + buf * 64 * KPAD;
#pragma unroll
        for (int ks = 0; ks < 8; ks++) {
#pragma unroll
            for (int ni = 0; ni < 8; ni++) {
                const float* kp = Kb + (ni * 8 + g) * KPAD + ks * 8 + cg;
                uint32_t b0 = f2tf32(kp[0]);
                uint32_t b1 = f2tf32(kp[4]);
                mma_tf32(sc[ni], qhi[ks][0], qhi[ks][1], qhi[ks][2], qhi[ks][3], b0, b1);
                mma_tf32(sc[ni], qlo[ks][0], qlo[ks][1], qlo[ks][2], qlo[ks][3], b0, b1);
            }
        }

        if (kt >= nkt - 2) {
            int row0 = q0 + wid * 16 + g;
            int row1 = row0 + 8;
#pragma unroll
            for (int ni = 0; ni < 8; ni++) {
                int col = kt * 64 + ni * 8 + 2 * cg;
                if (col     > row0) sc[ni][0] = -1e30f;
                if (col + 1 > row0) sc[ni][1] = -1e30f;
                if (col     > row1) sc[ni][2] = -1e30f;
                if (col + 1 > row1) sc[ni][3] = -1e30f;
            }
        }

        float mx0 = -1e30f, mx1 = -1e30f;
#pragma unroll
        for (int ni = 0; ni < 8; ni++) {
            mx0 = fmaxf(mx0, fmaxf(sc[ni][0], sc[ni][1]));
            mx1 = fmaxf(mx1, fmaxf(sc[ni][2], sc[ni][3]));
        }
        mx0 = fmaxf(mx0, __shfl_xor_sync(0xffffffffu, mx0, 1));
        mx0 = fmaxf(mx0, __shfl_xor_sync(0xffffffffu, mx0, 2));
        mx1 = fmaxf(mx1, __shfl_xor_sync(0xffffffffu, mx1, 1));
        mx1 = fmaxf(mx1, __shfl_xor_sync(0xffffffffu, mx1, 2));

        float mn0 = fmaxf(m0, mx0), mn1 = fmaxf(m1, mx1);
        float al0 = exp2f(m0 - mn0), al1 = exp2f(m1 - mn1);
        m0 = mn0; m1 = mn1;

        float ls0 = 0.0f, ls1 = 0.0f;
        float* Pw = Ps + (wid * 16 + g) * KPAD;
#pragma unroll
        for (int ni = 0; ni < 8; ni++) {
            float p0 = exp2f(sc[ni][0] - mn0);
            float p1 = exp2f(sc[ni][1] - mn0);
            float p2 = exp2f(sc[ni][2] - mn1);
            float p3 = exp2f(sc[ni][3] - mn1);
            ls0 += p0 + p1;
            ls1 += p2 + p3;
            float2 w0 = {p0, p1}, w1 = {p2, p3};
            *(float2*)(Pw + ni * 8 + 2 * cg) = w0;
            *(float2*)(Pw + 8 * KPAD + ni * 8 + 2 * cg) = w1;
        }
        ls0 += __shfl_xor_sync(0xffffffffu, ls0, 1);
        ls0 += __shfl_xor_sync(0xffffffffu, ls0, 2);
        ls1 += __shfl_xor_sync(0xffffffffu, ls1, 1);
        ls1 += __shfl_xor_sync(0xffffffffu, ls1, 2);
        l0 = l0 * al0 + ls0;
        l1 = l1 * al1 + ls1;
#pragma unroll
        for (int ni = 0; ni < 8; ni++) {
            o[ni][0] *= al0; o[ni][1] *= al0;
            o[ni][2] *= al1; o[ni][3] *= al1;
        }
        __syncthreads();

        const float* Vb = Vs + buf * 64 * KPAD;
#pragma unroll
        for (int ks = 0; ks < 8; ks++) {
            uint32_t a0 = f2tf32(Pw[ks * 8 + cg]);
            uint32_t a1 = f2tf32(Pw[8 * KPAD + ks * 8 + cg]);
            uint32_t a2 = f2tf32(Pw[ks * 8 + cg + 4]);
            uint32_t a3 = f2tf32(Pw[8 * KPAD + ks * 8 + cg + 4]);
#pragma unroll
            for (int ni = 0; ni < 8; ni++) {
                uint32_t b0 = f2tf32(Vb[(ks * 8 + cg) * KPAD + ni * 8 + g]);
                uint32_t b1 = f2tf32(Vb[(ks * 8 + cg + 4) * KPAD + ni * 8 + g]);
                mma_tf32(o[ni], a0, a1, a2, a3, b0, b1);
            }
        }
    }

    float il0 = 1.0f / l0, il1 = 1.0f / l1;
    int row0 = q0 + wid * 16 + g;
    float* yb = y + (size_t)b * TT * CC + (size_t)h * DD;
#pragma unroll
    for (int ni = 0; ni < 8; ni++) {
        int col = ni * 8 + 2 * cg;
        float2 w0 = {o[ni][0] * il0, o[ni][1] * il0};
        float2 w1 = {o[ni][2] * il1, o[ni][3] * il1};
        *(float2*)(yb + (size_t)row0 * CC + col) = w0;
        *(float2*)(yb + (size_t)(row0 + 8) * CC + col) = w1;
    }
}

// ---------------------------------------------------------------------------
// Launch
// ---------------------------------------------------------------------------
extern "C" void kernel_launch(void* const* d_in, const int* in_sizes, int n_in,
                              void* d_out, int out_size)
{
    const float* x  = (const float*)d_in[0];
    const float* We = (const float*)d_in[1];
    const float* be = (const float*)d_in[2];
    const float* Wp = (const float*)d_in[3];
    const float* bp = (const float*)d_in[4];
    float* out = (float*)d_out;

    float* qkv = nullptr;
    float* y = nullptr;
    cudaGetSymbolAddress((void**)&qkv, g_qkv);
    cudaGetSymbolAddress((void**)&y, g_y);

    static bool attr_done = false;
    if (!attr_done) {
        cudaFuncSetAttribute(gemm_bf16x3,
                             cudaFuncAttributeMaxDynamicSharedMemorySize,
                             GEMM_SMEM_BYTES);
        cudaFuncSetAttribute(flash_attn_tf32,
                             cudaFuncAttributeMaxDynamicSharedMemorySize,
                             FA_SMEM_BYTES);
        attr_done = true;
    }

    const int M = BB * TT;   // 4096

    // 1) QKV = x @ We^T + be   (3x bf16 tensor-core GEMM)
    gemm_bf16x3<<<dim3(3 * CC / 128, M / 128), 256, GEMM_SMEM_BYTES>>>(
        x, We, be, qkv, M, 3 * CC, CC);

    // 2) Flash attention (causal, tensor cores)
    flash_attn_tf32<<<dim3(TT / 128, HH, BB), 256, FA_SMEM_BYTES>>>(qkv, y);

    // 3) out = y @ Wp^T + bp
    gemm_bf16x3<<<dim3(CC / 128, M / 128), 256, GEMM_SMEM_BYTES>>>(
        y, Wp, bp, out, M, CC, CC);
}

// round 7
// speedup vs baseline: 2.7146x; 1.1648x over previous
#include <cuda_runtime.h>
#include <cstdint>

// Problem constants
#define BB 2
#define TT 2048
#define CC 1024
#define HH 16
#define DD 64

// Scratch (device globals: allocation-free)
__device__ float g_qkv[BB * TT * 3 * CC];   // [B, T, 3C]
__device__ float g_y[BB * TT * CC];         // [B, T, C]

// ---------------------------------------------------------------------------
// helpers
// ---------------------------------------------------------------------------
__device__ __forceinline__ void mma_bf16(float c[4],
    uint32_t a0, uint32_t a1, uint32_t a2, uint32_t a3,
    uint32_t b0, uint32_t b1)
{
    asm volatile(
        "mma.sync.aligned.m16n8k16.row.col.f32.bf16.bf16.f32 "
        "{%0,%1,%2,%3}, {%4,%5,%6,%7}, {%8,%9}, {%0,%1,%2,%3};\n"
        : "+f"(c[0]), "+f"(c[1]), "+f"(c[2]), "+f"(c[3])
        : "r"(a0), "r"(a1), "r"(a2), "r"(a3), "r"(b0), "r"(b1));
}

__device__ __forceinline__ void ldm4(uint32_t r[4], uint32_t addr) {
    asm volatile("ldmatrix.sync.aligned.m8n8.x4.shared.b16 {%0,%1,%2,%3}, [%4];"
                 : "=r"(r[0]), "=r"(r[1]), "=r"(r[2]), "=r"(r[3]) : "r"(addr));
}
__device__ __forceinline__ void ldm4t(uint32_t r[4], uint32_t addr) {
    asm volatile("ldmatrix.sync.aligned.m8n8.x4.trans.shared.b16 {%0,%1,%2,%3}, [%4];"
                 : "=r"(r[0]), "=r"(r[1]), "=r"(r[2]), "=r"(r[3]) : "r"(addr));
}

// pack two floats to bf16x2 (lo in low 16 bits)
__device__ __forceinline__ uint32_t pk2(float lo, float hi) {
    uint32_t r;
    asm("cvt.rn.bf16x2.f32 %0, %1, %2;" : "=r"(r) : "f"(hi), "f"(lo));
    return r;
}
// split packed pair: h = bf16x2(lo,hi), l = bf16x2 of residuals
__device__ __forceinline__ void bsplit2(float lo, float hi, uint32_t& h, uint32_t& l) {
    h = pk2(lo, hi);
    float rl = lo - __uint_as_float(h << 16);
    float rh = hi - __uint_as_float(h & 0xFFFF0000u);
    l = pk2(rl, rh);
}

// Split float4 into bf16 hi + lo residual, packed pairwise (memory order).
__device__ __forceinline__ void bsplit(float4 v, uint2& h, uint2& l) {
    uint32_t h01 = pk2(v.x, v.y);
    uint32_t h23 = pk2(v.z, v.w);
    float lx = v.x - __uint_as_float(h01 << 16);
    float ly = v.y - __uint_as_float(h01 & 0xFFFF0000u);
    float lz = v.z - __uint_as_float(h23 << 16);
    float lw = v.w - __uint_as_float(h23 & 0xFFFF0000u);
    h = make_uint2(h01, h23);
    l = make_uint2(pk2(lx, ly), pk2(lz, lw));
}

// ---------------------------------------------------------------------------
// NT GEMM (3x bf16, m16n8k16) — unchanged from R6.
// ---------------------------------------------------------------------------
#define GSTRIDE 80
#define TILE_B (128 * GSTRIDE)
#define BUF_B  (4 * TILE_B)
#define GEMM_SMEM_BYTES (2 * BUF_B)

__global__ __launch_bounds__(256, 2) void gemm_bf16x3(
    const float* __restrict__ A, const float* __restrict__ W,
    const float* __restrict__ bias, float* __restrict__ Cout,
    int M, int N, int K)
{
    extern __shared__ char smg[];
    const uint32_t sb = (uint32_t)__cvta_generic_to_shared(smg);
    const int tid  = threadIdx.x;
    const int wid  = tid >> 5;
    const int lane = tid & 31;
    const int g    = lane >> 2;
    const int cg   = lane & 3;
    const int wM   = wid >> 2;
    const int wN   = wid & 3;
    const int m0   = blockIdx.y * 128;
    const int n0   = blockIdx.x * 128;

    const uint32_t aoff = (uint32_t)(wM * 64 + (lane & 15)) * GSTRIDE + ((lane >> 4) * 16);
    const uint32_t boff = (uint32_t)(wN * 32 + ((lane & 16) >> 1) + (lane & 7)) * GSTRIDE
                        + ((lane & 8) * 2);

    float acc[4][4][4];
#pragma unroll
    for (int mi = 0; mi < 4; mi++)
#pragma unroll
        for (int ni = 0; ni < 4; ni++)
#pragma unroll
            for (int r = 0; r < 4; r++) acc[mi][ni][r] = 0.0f;

    const int NC = K / 32;
    float4 av[4], bv[4];

    auto load_regs = [&](int kc) {
        const int k0 = kc * 32;
#pragma unroll
        for (int i = 0; i < 4; i++) {
            int idx = i * 256 + tid, row = idx >> 3, c4 = (idx & 7) * 4;
            av[i] = *(const float4*)(A + (size_t)(m0 + row) * K + k0 + c4);
            bv[i] = *(const float4*)(W + (size_t)(n0 + row) * K + k0 + c4);
        }
    };
    auto sts_regs = [&](uint32_t bufoff) {
#pragma unroll
        for (int i = 0; i < 4; i++) {
            int idx = i * 256 + tid, row = idx >> 3, c4 = (idx & 7) * 4;
            uint32_t bo = (uint32_t)row * GSTRIDE + c4 * 2;
            uint2 h, l;
            bsplit(av[i], h, l);
            *(uint2*)(smg + bufoff + 0 * TILE_B + bo) = h;
            *(uint2*)(smg + bufoff + 1 * TILE_B + bo) = l;
            bsplit(bv[i], h, l);
            *(uint2*)(smg + bufoff + 2 * TILE_B + bo) = h;
            *(uint2*)(smg + bufoff + 3 * TILE_B + bo) = l;
        }
    };

    load_regs(0);
    sts_regs(0);
    __syncthreads();
    if (NC > 1) load_regs(1);

    for (int kc = 0; kc < NC; kc++) {
        const uint32_t bufo = (uint32_t)(kc & 1) * BUF_B;
        if (kc + 1 < NC) {
            sts_regs(bufo ^ BUF_B);
            if (kc + 2 < NC) load_regs(kc + 2);
        }

        const uint32_t ahB = sb + bufo + 0 * TILE_B + aoff;
        const uint32_t alB = sb + bufo + 1 * TILE_B + aoff;
        const uint32_t bhB = sb + bufo + 2 * TILE_B + boff;
        const uint32_t blB = sb + bufo + 3 * TILE_B + boff;

#pragma unroll
        for (int s = 0; s < 2; s++) {
            uint32_t ah[4][4], al[4][4], bh[2][4], bl[2][4];
#pragma unroll
            for (int mi = 0; mi < 4; mi++) {
                ldm4(ah[mi], ahB + mi * (16 * GSTRIDE) + s * 32);
                ldm4(al[mi], alB + mi * (16 * GSTRIDE) + s * 32);
            }
#pragma unroll
            for (int p = 0; p < 2; p++) {
                ldm4(bh[p], bhB + p * (16 * GSTRIDE) + s * 32);
                ldm4(bl[p], blB + p * (16 * GSTRIDE) + s * 32);
            }
#pragma unroll
            for (int mi = 0; mi < 4; mi++)
#pragma unroll
                for (int ni = 0; ni < 4; ni++) {
                    const int p = ni >> 1, hf = (ni & 1) * 2;
                    mma_bf16(acc[mi][ni], ah[mi][0], ah[mi][1], ah[mi][2], ah[mi][3],
                             bh[p][hf], bh[p][hf + 1]);
                    mma_bf16(acc[mi][ni], al[mi][0], al[mi][1], al[mi][2], al[mi][3],
                             bh[p][hf], bh[p][hf + 1]);
                    mma_bf16(acc[mi][ni], ah[mi][0], ah[mi][1], ah[mi][2], ah[mi][3],
                             bl[p][hf], bl[p][hf + 1]);
                }
        }
        __syncthreads();
    }

#pragma unroll
    for (int mi = 0; mi < 4; mi++) {
        int r0 = m0 + wM * 64 + mi * 16 + g;
#pragma unroll
        for (int ni = 0; ni < 4; ni++) {
            int col = n0 + wN * 32 + ni * 8 + 2 * cg;
            float b0v = bias[col], b1v = bias[col + 1];
            float2 o1 = { acc[mi][ni][0] + b0v, acc[mi][ni][1] + b1v };
            float2 o2 = { acc[mi][ni][2] + b0v, acc[mi][ni][3] + b1v };
            *(float2*)(Cout + (size_t)r0 * N + col) = o1;
            *(float2*)(Cout + (size_t)(r0 + 8) * N + col) = o2;
        }
    }
}

// ---------------------------------------------------------------------------
// Flash attention, bf16 tensor cores (3-pass QK and PV), causal.
// Block: 128 queries, 8 warps x 16 rows. Key tiles of 64, double-buffered.
// K/V pre-split to bf16 hi/lo smem; fragments via ldmatrix; P in registers.
// ---------------------------------------------------------------------------
#define ASTRIDE 144                     // bytes per 64-elem bf16 row (+16 pad)
#define ATILE (64 * ASTRIDE)            // 9216
#define ABUF  (4 * ATILE)               // Khi,Klo,Vhi,Vlo = 36864
#define FA_SMEM_BYTES (2 * ABUF)        // 73728

__global__ __launch_bounds__(256) void flash_attn_bf16(
    const float* __restrict__ qkv, float* __restrict__ y)
{
    extern __shared__ char sma[];
    const uint32_t sb = (uint32_t)__cvta_generic_to_shared(sma);

    const int qb = (gridDim.x - 1) - blockIdx.x;   // heavy tiles first
    const int h  = blockIdx.y;
    const int b  = blockIdx.z;
    const int tid  = threadIdx.x;
    const int wid  = tid >> 5;
    const int lane = tid & 31;
    const int g    = lane >> 2;
    const int cg   = lane & 3;
    const int q0   = qb * 128;
    const float* base = qkv + (size_t)b * TT * 3 * CC;

    // --- Q fragments (scale*log2e folded), bf16 hi/lo, loaded once from gmem
    uint32_t qh[4][4], ql[4][4];
    {
        const float QS = 0.125f * 1.44269504089f;
        const int r0 = q0 + wid * 16 + g;
        const float* Q0 = base + (size_t)r0 * (3 * CC) + h * DD;
        const float* Q8 = Q0 + (size_t)8 * (3 * CC);
#pragma unroll
        for (int ks = 0; ks < 4; ks++) {
            float2 v;
            v = *(const float2*)(Q0 + ks * 16 + 2 * cg);
            bsplit2(v.x * QS, v.y * QS, qh[ks][0], ql[ks][0]);
            v = *(const float2*)(Q8 + ks * 16 + 2 * cg);
            bsplit2(v.x * QS, v.y * QS, qh[ks][1], ql[ks][1]);
            v = *(const float2*)(Q0 + ks * 16 + 8 + 2 * cg);
            bsplit2(v.x * QS, v.y * QS, qh[ks][2], ql[ks][2]);
            v = *(const float2*)(Q8 + ks * 16 + 8 + 2 * cg);
            bsplit2(v.x * QS, v.y * QS, qh[ks][3], ql[ks][3]);
        }
    }

    // ldmatrix per-lane offsets (within a tile)
    // QK (non-trans): row = key, col = d
    const uint32_t koff = (uint32_t)((lane >> 4) * 8 + (lane & 7)) * ASTRIDE
                        + (((lane >> 3) & 1) * 16);
    // PV (trans): row = key, col = d
    const uint32_t voff = (uint32_t)(((lane >> 3) & 1) * 8 + (lane & 7)) * ASTRIDE
                        + ((lane >> 4) * 16);

    const int nkt = 2 * qb + 2;
    float4 kv[4], vv[4];

    auto load_regs = [&](int kt) {
        const int k0 = kt * 64;
#pragma unroll
        for (int i = 0; i < 4; i++) {
            int idx = i * 256 + tid, row = idx >> 4, c4 = (idx & 15) * 4;
            const float* kp = base + (size_t)(k0 + row) * (3 * CC) + CC + h * DD + c4;
            kv[i] = *(const float4*)kp;
            vv[i] = *(const float4*)(kp + CC);
        }
    };
    auto sts_regs = [&](uint32_t bufo) {
#pragma unroll
        for (int i = 0; i < 4; i++) {
            int idx = i * 256 + tid, row = idx >> 4, c4 = (idx & 15) * 4;
            uint32_t bo = (uint32_t)row * ASTRIDE + c4 * 2;
            uint2 hh, ll;
            bsplit(kv[i], hh, ll);
            *(uint2*)(sma + bufo + 0 * ATILE + bo) = hh;
            *(uint2*)(sma + bufo + 1 * ATILE + bo) = ll;
            bsplit(vv[i], hh, ll);
            *(uint2*)(sma + bufo + 2 * ATILE + bo) = hh;
            *(uint2*)(sma + bufo + 3 * ATILE + bo) = ll;
        }
    };

    // prime: tile 0 -> buf0
    load_regs(0);
    sts_regs(0);
    __syncthreads();
    if (nkt > 1) load_regs(1);

    float m0 = -1e30f, m1 = -1e30f, l0 = 0.0f, l1 = 0.0f;
    float o[8][4];
#pragma unroll
    for (int ni = 0; ni < 8; ni++)
#pragma unroll
        for (int r = 0; r < 4; r++) o[ni][r] = 0.0f;

    for (int kt = 0; kt < nkt; kt++) {
        const uint32_t bufo = (uint32_t)(kt & 1) * ABUF;
        const uint32_t khB = sb + bufo + 0 * ATILE + koff;
        const uint32_t klB = sb + bufo + 1 * ATILE + koff;
        const uint32_t vhB = sb + bufo + 2 * ATILE + voff;
        const uint32_t vlB = sb + bufo + 3 * ATILE + voff;

        // ---- S = Q K^T (3-pass bf16)
        float sc[8][4];
#pragma unroll
        for (int ni = 0; ni < 8; ni++)
#pragma unroll
            for (int r = 0; r < 4; r++) sc[ni][r] = 0.0f;

#pragma unroll
        for (int ks = 0; ks < 4; ks++) {
#pragma unroll
            for (int np = 0; np < 4; np++) {
                uint32_t bh[4], bl[4];
                ldm4(bh, khB + np * (16 * ASTRIDE) + ks * 32);
                ldm4(bl, klB + np * (16 * ASTRIDE) + ks * 32);
                mma_bf16(sc[2*np],   qh[ks][0], qh[ks][1], qh[ks][2], qh[ks][3], bh[0], bh[1]);
                mma_bf16(sc[2*np],   ql[ks][0], ql[ks][1], ql[ks][2], ql[ks][3], bh[0], bh[1]);
                mma_bf16(sc[2*np],   qh[ks][0], qh[ks][1], qh[ks][2], qh[ks][3], bl[0], bl[1]);
                mma_bf16(sc[2*np+1], qh[ks][0], qh[ks][1], qh[ks][2], qh[ks][3], bh[2], bh[3]);
                mma_bf16(sc[2*np+1], ql[ks][0], ql[ks][1], ql[ks][2], ql[ks][3], bh[2], bh[3]);
                mma_bf16(sc[2*np+1], qh[ks][0], qh[ks][1], qh[ks][2], qh[ks][3], bl[2], bl[3]);
            }
        }

        // ---- causal mask (last two key tiles only)
        if (kt >= nkt - 2) {
            int row0 = q0 + wid * 16 + g;
            int row1 = row0 + 8;
#pragma unroll
            for (int ni = 0; ni < 8; ni++) {
                int col = kt * 64 + ni * 8 + 2 * cg;
                if (col     > row0) sc[ni][0] = -1e30f;
                if (col + 1 > row0) sc[ni][1] = -1e30f;
                if (col     > row1) sc[ni][2] = -1e30f;
                if (col + 1 > row1) sc[ni][3] = -1e30f;
            }
        }

        // ---- online softmax (base 2)
        float mx0 = -1e30f, mx1 = -1e30f;
#pragma unroll
        for (int ni = 0; ni < 8; ni++) {
            mx0 = fmaxf(mx0, fmaxf(sc[ni][0], sc[ni][1]));
            mx1 = fmaxf(mx1, fmaxf(sc[ni][2], sc[ni][3]));
        }
        mx0 = fmaxf(mx0, __shfl_xor_sync(0xffffffffu, mx0, 1));
        mx0 = fmaxf(mx0, __shfl_xor_sync(0xffffffffu, mx0, 2));
        mx1 = fmaxf(mx1, __shfl_xor_sync(0xffffffffu, mx1, 1));
        mx1 = fmaxf(mx1, __shfl_xor_sync(0xffffffffu, mx1, 2));

        float mn0 = fmaxf(m0, mx0), mn1 = fmaxf(m1, mx1);
        float al0 = exp2f(m0 - mn0), al1 = exp2f(m1 - mn1);
        m0 = mn0; m1 = mn1;

        float ls0 = 0.0f, ls1 = 0.0f;
#pragma unroll
        for (int ni = 0; ni < 8; ni++) {
            sc[ni][0] = exp2f(sc[ni][0] - mn0);
            sc[ni][1] = exp2f(sc[ni][1] - mn0);
            sc[ni][2] = exp2f(sc[ni][2] - mn1);
            sc[ni][3] = exp2f(sc[ni][3] - mn1);
            ls0 += sc[ni][0] + sc[ni][1];
            ls1 += sc[ni][2] + sc[ni][3];
        }
        ls0 += __shfl_xor_sync(0xffffffffu, ls0, 1);
        ls0 += __shfl_xor_sync(0xffffffffu, ls0, 2);
        ls1 += __shfl_xor_sync(0xffffffffu, ls1, 1);
        ls1 += __shfl_xor_sync(0xffffffffu, ls1, 2);
        l0 = l0 * al0 + ls0;
        l1 = l1 * al1 + ls1;
#pragma unroll
        for (int ni = 0; ni < 8; ni++) {
            o[ni][0] *= al0; o[ni][1] *= al0;
            o[ni][2] *= al1; o[ni][3] *= al1;
        }

        // ---- pack P into bf16 A fragments (registers only)
        uint32_t ph[4][4], pl[4][4];
#pragma unroll
        for (int j = 0; j < 4; j++) {
            bsplit2(sc[2*j][0],   sc[2*j][1],   ph[j][0], pl[j][0]);
            bsplit2(sc[2*j][2],   sc[2*j][3],   ph[j][1], pl[j][1]);
            bsplit2(sc[2*j+1][0], sc[2*j+1][1], ph[j][2], pl[j][2]);
            bsplit2(sc[2*j+1][2], sc[2*j+1][3], ph[j][3], pl[j][3]);
        }

        // ---- O += P V (3-pass bf16), V fragments via ldmatrix.trans
#pragma unroll
        for (int j = 0; j < 4; j++) {
#pragma unroll
            for (int dp = 0; dp < 4; dp++) {
                uint32_t bh[4], bl[4];
                ldm4t(bh, vhB + j * (16 * ASTRIDE) + dp * 32);
                ldm4t(bl, vlB + j * (16 * ASTRIDE) + dp * 32);
                mma_bf16(o[2*dp],   ph[j][0], ph[j][1], ph[j][2], ph[j][3], bh[0], bh[1]);
                mma_bf16(o[2*dp],   pl[j][0], pl[j][1], pl[j][2], pl[j][3], bh[0], bh[1]);
                mma_bf16(o[2*dp],   ph[j][0], ph[j][1], ph[j][2], ph[j][3], bl[0], bl[1]);
                mma_bf16(o[2*dp+1], ph[j][0], ph[j][1], ph[j][2], ph[j][3], bh[2], bh[3]);
                mma_bf16(o[2*dp+1], pl[j][0], pl[j][1], pl[j][2], pl[j][3], bh[2], bh[3]);
                mma_bf16(o[2*dp+1], ph[j][0], ph[j][1], ph[j][2], ph[j][3], bl[2], bl[3]);
            }
        }

        // ---- stage next tile into the other buffer
        if (kt + 1 < nkt) {
            sts_regs(bufo ^ ABUF);
            if (kt + 2 < nkt) load_regs(kt + 2);
        }
        __syncthreads();
    }

    // ---- epilogue
    float il0 = 1.0f / l0, il1 = 1.0f / l1;
    int row0 = q0 + wid * 16 + g;
    float* yb = y + (size_t)b * TT * CC + (size_t)h * DD;
#pragma unroll
    for (int ni = 0; ni < 8; ni++) {
        int col = ni * 8 + 2 * cg;
        float2 w0 = {o[ni][0] * il0, o[ni][1] * il0};
        float2 w1 = {o[ni][2] * il1, o[ni][3] * il1};
        *(float2*)(yb + (size_t)row0 * CC + col) = w0;
        *(float2*)(yb + (size_t)(row0 + 8) * CC + col) = w1;
    }
}

// ---------------------------------------------------------------------------
// Launch
// ---------------------------------------------------------------------------
extern "C" void kernel_launch(void* const* d_in, const int* in_sizes, int n_in,
                              void* d_out, int out_size)
{
    const float* x  = (const float*)d_in[0];
    const float* We = (const float*)d_in[1];
    const float* be = (const float*)d_in[2];
    const float* Wp = (const float*)d_in[3];
    const float* bp = (const float*)d_in[4];
    float* out = (float*)d_out;

    float* qkv = nullptr;
    float* y = nullptr;
    cudaGetSymbolAddress((void**)&qkv, g_qkv);
    cudaGetSymbolAddress((void**)&y, g_y);

    static bool attr_done = false;
    if (!attr_done) {
        cudaFuncSetAttribute(gemm_bf16x3,
                             cudaFuncAttributeMaxDynamicSharedMemorySize,
                             GEMM_SMEM_BYTES);
        cudaFuncSetAttribute(flash_attn_bf16,
                             cudaFuncAttributeMaxDynamicSharedMemorySize,
                             FA_SMEM_BYTES);
        attr_done = true;
    }

    const int M = BB * TT;   // 4096

    // 1) QKV = x @ We^T + be
    gemm_bf16x3<<<dim3(3 * CC / 128, M / 128), 256, GEMM_SMEM_BYTES>>>(
        x, We, be, qkv, M, 3 * CC, CC);

    // 2) Flash attention (causal, bf16 tensor cores)
    flash_attn_bf16<<<dim3(TT / 128, HH, BB), 256, FA_SMEM_BYTES>>>(qkv, y);

    // 3) out = y @ Wp^T + bp
    gemm_bf16x3<<<dim3(CC / 128, M / 128), 256, GEMM_SMEM_BYTES>>>(
        y, Wp, bp, out, M, CC, CC);
}